// round 7
// baseline (speedup 1.0000x reference)
#include <cuda_runtime.h>
#include <cuda_fp16.h>
#include <math.h>

#define H2 2048
#define T_STEPS 2048
#define NG 8192            // 4*H2
#define LAYERS 4
#define JJ 14              // h-elements per CTA
#define ROWS 56            // 4*JJ gate rows per CTA
#define NCTA 147           // ceil(2048/14)
#define SCAN_THREADS 512
#define SCAN_SMEM (ROWS * H2 * 2)   // 229376 bytes of fp16 weights
#define BGROUPS 16                  // barrier tree fan-in groups

// ---------------- scratch (static device globals; no allocation) ----------------
__device__ float  g_xw[(size_t)T_STEPS * NG];        // 67 MB: xw for current layer
__device__ __align__(16) __half g_hseq[(size_t)T_STEPS * H2]; // h sequence (fp16) of current layer
__device__ __align__(16) __half g_hbuf[2][H2];       // double-buffered h for the scan
__device__ float  g_hlast[H2];                       // fp32 h at t=T-1
// tree barrier state: 16 group counters padded 128B apart + root + generation
__device__ unsigned g_cnt1[BGROUPS * 32];
__device__ unsigned g_cnt_root = 0;
__device__ unsigned g_gen      = 0;

// ---------------- helpers ----------------
static __device__ __forceinline__ float2 h2_to_f2(unsigned u) {
    __half2 h;
    *reinterpret_cast<unsigned*>(&h) = u;
    return __half22float2(h);
}
static __device__ __forceinline__ __half2 u2h2(unsigned u) {
    __half2 h;
    *reinterpret_cast<unsigned*>(&h) = u;
    return h;
}
static __device__ __forceinline__ uint4 ldcg_v4(const uint4* p) {
    uint4 v;
    asm volatile("ld.global.cg.v4.u32 {%0,%1,%2,%3}, [%4];"
                 : "=r"(v.x), "=r"(v.y), "=r"(v.z), "=r"(v.w) : "l"(p));
    return v;
}
static __device__ __forceinline__ unsigned ld_cg_u32(const unsigned* p) {
    unsigned v;
    asm volatile("ld.global.cg.u32 %0, [%1];" : "=r"(v) : "l"(p));
    return v;
}
static __device__ __forceinline__ float sigmoidf_fast(float x) {
    return 1.0f / (1.0f + __expf(-x));
}
static __device__ __forceinline__ float tanhf_fast(float x) {
    return 2.0f / (1.0f + __expf(-2.0f * x)) - 1.0f;
}

// tree grid barrier, thread 0 of each CTA only. Self-resetting counters
// (graph-replay safe); generation is monotone across launches/replays.
// Arrivals spread over BGROUPS distinct L2 lines (atomics to a single address
// serialize at ~27 cyc each at the LTS); poll is a plain .cg LOAD, not an atomic.
static __device__ __forceinline__ void grid_bar(unsigned& my_gen, int bid) {
    my_gen += 1;
    const int g = bid & (BGROUPS - 1);
    const unsigned gsz = (g < (NCTA & (BGROUPS - 1))) ? (NCTA / BGROUPS + 1)
                                                      : (NCTA / BGROUPS);
    unsigned old = atomicAdd(&g_cnt1[g * 32], 1);
    if (old == gsz - 1) {
        atomicExch(&g_cnt1[g * 32], 0);          // safe: next-phase arrivals gated by g_gen
        unsigned o2 = atomicAdd(&g_cnt_root, 1);
        if (o2 == BGROUPS - 1) {
            atomicExch(&g_cnt_root, 0);
            __threadfence();
            atomicExch(&g_gen, my_gen);          // release the generation
        }
    }
    if ((int)(ld_cg_u32(&g_gen) - my_gen) < 0) {
        while ((int)(ld_cg_u32(&g_gen) - my_gen) < 0) { __nanosleep(40); }
    }
    __threadfence();                             // acquire: h writes from all CTAs visible
}

// ---------------- layer-0 xw: xw[t][r] = event[t]*w_ih0[r] + b_ih[r] + b_hh[r] ----------------
__global__ void xw0_kernel(const float* __restrict__ event, const float* __restrict__ w0,
                           const float* __restrict__ bih, const float* __restrict__ bhh) {
    int t = blockIdx.y;
    int c = (blockIdx.x * blockDim.x + threadIdx.x) * 4;
    float e = event[t];
    float4 w  = *(const float4*)(w0 + c);
    float4 bi = *(const float4*)(bih + c);
    float4 bh = *(const float4*)(bhh + c);
    float4 r;
    r.x = fmaf(e, w.x, bi.x + bh.x);
    r.y = fmaf(e, w.y, bi.y + bh.y);
    r.z = fmaf(e, w.z, bi.z + bh.z);
    r.w = fmaf(e, w.w, bi.w + bh.w);
    *(float4*)(g_xw + (size_t)t * NG + c) = r;
}

// ---------------- xw GEMM: g_xw[t][r] = sum_k g_hseq[t][k] * B[r][k] + bias[r] ----------------
#define BM 128
#define BN 128
#define BK 32
#define SPAD 4

__global__ __launch_bounds__(256, 2) void gemm_xw(const float* __restrict__ B,
                                                  const float* __restrict__ bih,
                                                  const float* __restrict__ bhh) {
    __shared__ float As[BK][BM + SPAD];
    __shared__ float Bs[BK][BN + SPAD];
    const int tid = threadIdx.x;
    const int tx = tid & 15;
    const int ty = tid >> 4;
    const int row0 = blockIdx.y * BM;   // t
    const int col0 = blockIdx.x * BN;   // r

    const int lr = tid >> 1;            // 0..127 (tile row for loads)
    const int lc = (tid & 1) * 16;      // 0 or 16 (k offset for loads)
    const __half* aptr = g_hseq + (size_t)(row0 + lr) * H2 + lc;
    const float*  bptr = B      + (size_t)(col0 + lr) * H2 + lc;

    float acc[8][8];
#pragma unroll
    for (int i = 0; i < 8; i++)
#pragma unroll
        for (int j = 0; j < 8; j++) acc[i][j] = 0.0f;

    for (int k0 = 0; k0 < H2; k0 += BK) {
        uint4 a0 = *(const uint4*)(aptr + k0);
        uint4 a1 = *(const uint4*)(aptr + k0 + 8);
        float4 b0 = *(const float4*)(bptr + k0);
        float4 b1 = *(const float4*)(bptr + k0 + 4);
        float4 b2 = *(const float4*)(bptr + k0 + 8);
        float4 b3 = *(const float4*)(bptr + k0 + 12);
        __syncthreads();
        {
            unsigned aw[8] = {a0.x, a0.y, a0.z, a0.w, a1.x, a1.y, a1.z, a1.w};
#pragma unroll
            for (int e = 0; e < 8; e++) {
                float2 f = h2_to_f2(aw[e]);
                As[lc + 2 * e][lr]     = f.x;
                As[lc + 2 * e + 1][lr] = f.y;
            }
            float bw[16] = {b0.x, b0.y, b0.z, b0.w, b1.x, b1.y, b1.z, b1.w,
                            b2.x, b2.y, b2.z, b2.w, b3.x, b3.y, b3.z, b3.w};
#pragma unroll
            for (int e = 0; e < 16; e++) Bs[lc + e][lr] = bw[e];
        }
        __syncthreads();
#pragma unroll
        for (int k = 0; k < BK; k++) {
            float4 xa = *(const float4*)&As[k][ty * 8];
            float4 xb = *(const float4*)&As[k][ty * 8 + 4];
            float4 ya = *(const float4*)&Bs[k][tx * 8];
            float4 yb = *(const float4*)&Bs[k][tx * 8 + 4];
            float av[8] = {xa.x, xa.y, xa.z, xa.w, xb.x, xb.y, xb.z, xb.w};
            float bv[8] = {ya.x, ya.y, ya.z, ya.w, yb.x, yb.y, yb.z, yb.w};
#pragma unroll
            for (int i = 0; i < 8; i++)
#pragma unroll
                for (int j = 0; j < 8; j++) acc[i][j] = fmaf(av[i], bv[j], acc[i][j]);
        }
    }

    float bias[8];
#pragma unroll
    for (int j = 0; j < 8; j++) {
        int c = col0 + tx * 8 + j;
        bias[j] = __ldg(bih + c) + __ldg(bhh + c);
    }
#pragma unroll
    for (int i = 0; i < 8; i++) {
        float* crow = g_xw + (size_t)(row0 + ty * 8 + i) * NG + col0 + tx * 8;
        float4 v0 = {acc[i][0] + bias[0], acc[i][1] + bias[1], acc[i][2] + bias[2], acc[i][3] + bias[3]};
        float4 v1 = {acc[i][4] + bias[4], acc[i][5] + bias[5], acc[i][6] + bias[6], acc[i][7] + bias[7]};
        *(float4*)crow = v0;
        *(float4*)(crow + 4) = v1;
    }
}

// ---------------- persistent LSTM scan (512 thr, K-split, HFMA2, tree barrier) ----------------
__global__ __launch_bounds__(SCAN_THREADS, 1) void lstm_scan(const float* __restrict__ whh,
                                                             int last_layer) {
    extern __shared__ __align__(16) unsigned char smem_raw[];
    __half2* wsh = (__half2*)smem_raw;          // ROWS x 1024 half2
    __shared__ float gpart[2][ROWS];
    __shared__ float cst[JJ];

    const int tid  = threadIdx.x;
    const int lane = tid & 31;
    const int warp = tid >> 5;
    const int grp  = warp & 7;
    const int khalf = warp >> 3;
    const int koff = khalf * 128;               // uint4 offset into a row (256 uint4/row)
    const int j0   = blockIdx.x * JJ;
    const int nj   = (H2 - j0 < JJ) ? (H2 - j0) : JJ;

    unsigned my_gen = 0;
    if (tid == 0) my_gen = ld_cg_u32(&g_gen);

    // load + convert this CTA's 56 weight rows into SMEM (row r = gate*JJ + jl)
    for (int r = warp; r < ROWS; r += 16) {
        int gate = r / JJ;
        int jl = r - gate * JJ;
        __half2* dst = wsh + r * (H2 / 2);
        if (jl < nj) {
            const float2* src = (const float2*)(whh + ((size_t)gate * H2 + j0 + jl) * H2);
            for (int p = lane; p < H2 / 2; p += 32) {
                float2 v = __ldg(src + p);
                dst[p] = __floats2half2_rn(v.x, v.y);
            }
        } else {
            for (int p = lane; p < H2 / 2; p += 32) dst[p] = __half2half2(__float2half(0.0f));
        }
    }
    if (tid < JJ) cst[tid] = 0.0f;
    __syncthreads();

    const uint4* wbase = (const uint4*)smem_raw;

    for (int t = 0; t < T_STEPS; ++t) {
        // prefetch xw for this CTA's gate entries (combine uses them later)
        float xwi = 0.f, xwf = 0.f, xwg = 0.f, xwo = 0.f;
        if (tid < nj) {
            const float* xwt = g_xw + (size_t)t * NG + j0 + tid;
            xwi = __ldg(xwt);
            xwf = __ldg(xwt + H2);
            xwg = __ldg(xwt + 2 * H2);
            xwo = __ldg(xwt + 3 * H2);
        }

        // load this warp's K-half of h_{t-1} (fp16, L2-coherent .cg): 16 half2 regs
        const uint4* hb = ((const uint4*)(&g_hbuf[t & 1][0])) + koff;
        uint4 hu0 = ldcg_v4(hb + lane);
        uint4 hu1 = ldcg_v4(hb + lane + 32);
        uint4 hu2 = ldcg_v4(hb + lane + 64);
        uint4 hu3 = ldcg_v4(hb + lane + 96);
        __half2 hh[16];
        hh[0]=u2h2(hu0.x); hh[1]=u2h2(hu0.y); hh[2]=u2h2(hu0.z); hh[3]=u2h2(hu0.w);
        hh[4]=u2h2(hu1.x); hh[5]=u2h2(hu1.y); hh[6]=u2h2(hu1.z); hh[7]=u2h2(hu1.w);
        hh[8]=u2h2(hu2.x); hh[9]=u2h2(hu2.y); hh[10]=u2h2(hu2.z); hh[11]=u2h2(hu2.w);
        hh[12]=u2h2(hu3.x); hh[13]=u2h2(hu3.y); hh[14]=u2h2(hu3.z); hh[15]=u2h2(hu3.w);

        // 7 dot-product rows per warp, over this warp's K-half
#pragma unroll
        for (int rr = 0; rr < 7; rr++) {
            int r = grp * 7 + rr;
            const uint4* wr = wbase + (size_t)r * 256 + koff;
            uint4 wv0 = wr[lane];
            uint4 wv1 = wr[lane + 32];
            uint4 wv2 = wr[lane + 64];
            uint4 wv3 = wr[lane + 96];
            __half2 zero = __half2half2(__float2half(0.0f));
            __half2 a0 = zero, a1 = zero, a2 = zero, a3 = zero;
            a0 = __hfma2(u2h2(wv0.x), hh[0],  a0);
            a1 = __hfma2(u2h2(wv0.y), hh[1],  a1);
            a2 = __hfma2(u2h2(wv0.z), hh[2],  a2);
            a3 = __hfma2(u2h2(wv0.w), hh[3],  a3);
            a0 = __hfma2(u2h2(wv1.x), hh[4],  a0);
            a1 = __hfma2(u2h2(wv1.y), hh[5],  a1);
            a2 = __hfma2(u2h2(wv1.z), hh[6],  a2);
            a3 = __hfma2(u2h2(wv1.w), hh[7],  a3);
            a0 = __hfma2(u2h2(wv2.x), hh[8],  a0);
            a1 = __hfma2(u2h2(wv2.y), hh[9],  a1);
            a2 = __hfma2(u2h2(wv2.z), hh[10], a2);
            a3 = __hfma2(u2h2(wv2.w), hh[11], a3);
            a0 = __hfma2(u2h2(wv3.x), hh[12], a0);
            a1 = __hfma2(u2h2(wv3.y), hh[13], a1);
            a2 = __hfma2(u2h2(wv3.z), hh[14], a2);
            a3 = __hfma2(u2h2(wv3.w), hh[15], a3);
            float2 f0 = __half22float2(a0);
            float2 f1 = __half22float2(a1);
            float2 f2 = __half22float2(a2);
            float2 f3 = __half22float2(a3);
            float a = ((f0.x + f0.y) + (f1.x + f1.y)) + ((f2.x + f2.y) + (f3.x + f3.y));
#pragma unroll
            for (int o = 16; o; o >>= 1) a += __shfl_xor_sync(0xffffffffu, a, o);
            if (lane == 0) gpart[khalf][r] = a;
        }
        __syncthreads();

        // gate combine + publish (warp 0 only), then tree grid barrier by thread 0
        if (warp == 0) {
            if (lane < nj) {
                int jl = lane;
                float gi = gpart[0][0 * JJ + jl] + gpart[1][0 * JJ + jl] + xwi;
                float gf = gpart[0][1 * JJ + jl] + gpart[1][1 * JJ + jl] + xwf;
                float gg = gpart[0][2 * JJ + jl] + gpart[1][2 * JJ + jl] + xwg;
                float go = gpart[0][3 * JJ + jl] + gpart[1][3 * JJ + jl] + xwo;
                float c = sigmoidf_fast(gf) * cst[jl] + sigmoidf_fast(gi) * tanhf_fast(gg);
                float h = sigmoidf_fast(go) * tanhf_fast(c);
                cst[jl] = c;
                int j = j0 + jl;
                __half hhv = __float2half_rn(h);
                g_hbuf[(t + 1) & 1][j] = hhv;                 // for next step's matvec
                g_hseq[(size_t)t * H2 + j] = hhv;             // for next layer's GEMM
                if (last_layer && t == T_STEPS - 1) g_hlast[j] = h;
            }
            __syncwarp();
            if (lane == 0) {
                __threadfence();                              // release h writes
                grid_bar(my_gen, blockIdx.x);
            }
        }
        __syncthreads();
    }
}

// ---------------- final projection + log_softmax ----------------
__global__ void final_kernel(const float* __restrict__ wout, const float* __restrict__ bout,
                             float* __restrict__ out) {
    int tid = threadIdx.x;
    float s0 = 0.f, s1 = 0.f;
    for (int k = tid; k < H2; k += 256) {
        float h = g_hlast[k];
        s0 = fmaf(h, wout[k], s0);
        s1 = fmaf(h, wout[H2 + k], s1);
    }
    __shared__ float r0[8], r1[8];
#pragma unroll
    for (int o = 16; o; o >>= 1) {
        s0 += __shfl_xor_sync(0xffffffffu, s0, o);
        s1 += __shfl_xor_sync(0xffffffffu, s1, o);
    }
    if ((tid & 31) == 0) { r0[tid >> 5] = s0; r1[tid >> 5] = s1; }
    __syncthreads();
    if (tid == 0) {
        float l0 = bout[0], l1 = bout[1];
        for (int w = 0; w < 8; w++) { l0 += r0[w]; l1 += r1[w]; }
        float m = fmaxf(l0, l1);
        float z = expf(l0 - m) + expf(l1 - m);
        float lse = m + logf(z);
        out[0] = l0 - lse;
        out[1] = l1 - lse;
    }
}

// ---------------- launcher ----------------
extern "C" void kernel_launch(void* const* d_in, const int* in_sizes, int n_in,
                              void* d_out, int out_size) {
    const float* event = (const float*)d_in[0];
    const float* w_ih0 = (const float*)d_in[1];   // (8192, 1)
    const float* w_ih  = (const float*)d_in[2];   // (3, 8192, 2048)
    const float* w_hh  = (const float*)d_in[3];   // (4, 8192, 2048)
    const float* b_ih  = (const float*)d_in[4];   // (4, 8192)
    const float* b_hh  = (const float*)d_in[5];   // (4, 8192)
    const float* w_out = (const float*)d_in[6];   // (2, 2048)
    const float* b_out = (const float*)d_in[7];   // (2,)
    float* out = (float*)d_out;

    cudaFuncSetAttribute(lstm_scan, cudaFuncAttributeMaxDynamicSharedMemorySize, SCAN_SMEM);

    void* hbuf_ptr = nullptr;
    cudaGetSymbolAddress(&hbuf_ptr, g_hbuf);

    for (int l = 0; l < LAYERS; ++l) {
        if (l == 0) {
            dim3 grid(NG / (256 * 4), T_STEPS);
            xw0_kernel<<<grid, 256>>>(event, w_ih0, b_ih, b_hh);
        } else {
            dim3 grid(NG / BN, T_STEPS / BM);
            gemm_xw<<<grid, 256>>>(w_ih + (size_t)(l - 1) * NG * H2,
                                   b_ih + (size_t)l * NG,
                                   b_hh + (size_t)l * NG);
        }
        cudaMemsetAsync(hbuf_ptr, 0, 2 * H2 * sizeof(__half));
        lstm_scan<<<NCTA, SCAN_THREADS, SCAN_SMEM>>>(w_hh + (size_t)l * NG * H2,
                                                     (l == LAYERS - 1) ? 1 : 0);
    }
    final_kernel<<<1, 256>>>(w_out, b_out, out);
}

// round 9
// speedup vs baseline: 1.0535x; 1.0535x over previous
#include <cuda_runtime.h>
#include <cuda_fp16.h>
#include <math.h>

#define H2 2048
#define T_STEPS 2048
#define NG 8192            // 4*H2
#define LAYERS 4
#define JJ 14              // h-elements per CTA
#define ROWS 56            // 4*JJ gate rows per CTA
#define NCTA 147           // ceil(2048/14)
#define SCAN_THREADS 1024
#define SMEM_ROWS 55                      // rows kept in SMEM (row 55 streamed via L1)
#define SCAN_SMEM (SMEM_ROWS * H2 * 2)    // 225280 bytes of fp16 weights

// ---------------- scratch (static device globals; no allocation) ----------------
__device__ float  g_xw[(size_t)T_STEPS * NG];        // 67 MB: xw for current layer
__device__ __align__(16) __half g_hseq[(size_t)T_STEPS * H2]; // h sequence (fp16)
__device__ __align__(16) __half g_hbuf[2][H2];       // double-buffered h for the scan
__device__ __align__(16) __half g_wext[(size_t)LAYERS * NCTA * H2]; // per-CTA extra row (fp16)
__device__ float  g_hlast[H2];                       // fp32 h at t=T-1
__device__ unsigned g_bar_count = 0;
__device__ unsigned g_bar_gen   = 0;

// ---------------- helpers ----------------
static __device__ __forceinline__ float2 h2_to_f2(unsigned u) {
    __half2 h;
    *reinterpret_cast<unsigned*>(&h) = u;
    return __half22float2(h);
}
static __device__ __forceinline__ __half2 u2h2(unsigned u) {
    __half2 h;
    *reinterpret_cast<unsigned*>(&h) = u;
    return h;
}
static __device__ __forceinline__ uint4 ldcg_v4(const uint4* p) {
    uint4 v;
    asm volatile("ld.global.cg.v4.u32 {%0,%1,%2,%3}, [%4];"
                 : "=r"(v.x), "=r"(v.y), "=r"(v.z), "=r"(v.w) : "l"(p));
    return v;
}
static __device__ __forceinline__ unsigned ld_cg_u32(const unsigned* p) {
    unsigned v;
    asm volatile("ld.global.cg.u32 %0, [%1];" : "=r"(v) : "l"(p));
    return v;
}
static __device__ __forceinline__ float sigmoidf_fast(float x) {
    return 1.0f / (1.0f + __expf(-x));
}
static __device__ __forceinline__ float tanhf_fast(float x) {
    return 2.0f / (1.0f + __expf(-2.0f * x)) - 1.0f;
}

// flat grid barrier (thread 0 of each CTA): atomic arrivals to one counter,
// non-atomic .cg poll of the generation word. Self-resetting; replay safe.
static __device__ __forceinline__ void grid_bar(unsigned& my_gen, unsigned nct) {
    my_gen += 1;
    unsigned old = atomicAdd(&g_bar_count, 1);
    if (old == nct - 1) {
        atomicExch(&g_bar_count, 0);
        __threadfence();
        atomicAdd(&g_bar_gen, 1);               // release
    }
    if ((int)(ld_cg_u32(&g_bar_gen) - my_gen) < 0) {
        while ((int)(ld_cg_u32(&g_bar_gen) - my_gen) < 0) { __nanosleep(32); }
    }
    __threadfence();                            // acquire
}

// ---------------- pack per-CTA extra weight row (gate o, jl=13) to fp16 ----------------
__global__ void pack_extra(const float* __restrict__ whh) {
    int k = blockIdx.x;          // CTA index
    int l = blockIdx.y;          // layer
    int j = JJ * k + JJ - 1;     // h index of the extra row
    __half* dst = g_wext + ((size_t)l * NCTA + k) * H2;
    if (j >= H2) {
        for (int i = threadIdx.x; i < H2; i += 256) dst[i] = __float2half(0.0f);
        return;
    }
    const float* src = whh + ((size_t)l * NG + 3 * H2 + j) * H2;
    for (int i = threadIdx.x; i < H2; i += 256) dst[i] = __float2half_rn(src[i]);
}

// ---------------- layer-0 xw: xw[t][r] = event[t]*w_ih0[r] + b_ih[r] + b_hh[r] ----------------
__global__ void xw0_kernel(const float* __restrict__ event, const float* __restrict__ w0,
                           const float* __restrict__ bih, const float* __restrict__ bhh) {
    int t = blockIdx.y;
    int c = (blockIdx.x * blockDim.x + threadIdx.x) * 4;
    float e = event[t];
    float4 w  = *(const float4*)(w0 + c);
    float4 bi = *(const float4*)(bih + c);
    float4 bh = *(const float4*)(bhh + c);
    float4 r;
    r.x = fmaf(e, w.x, bi.x + bh.x);
    r.y = fmaf(e, w.y, bi.y + bh.y);
    r.z = fmaf(e, w.z, bi.z + bh.z);
    r.w = fmaf(e, w.w, bi.w + bh.w);
    *(float4*)(g_xw + (size_t)t * NG + c) = r;
}

// ---------------- xw GEMM: g_xw[t][r] = sum_k g_hseq[t][k] * B[r][k] + bias[r] ----------------
#define BM 128
#define BN 128
#define BK 32
#define SPAD 4

__global__ __launch_bounds__(256, 2) void gemm_xw(const float* __restrict__ B,
                                                  const float* __restrict__ bih,
                                                  const float* __restrict__ bhh) {
    __shared__ float As[BK][BM + SPAD];
    __shared__ float Bs[BK][BN + SPAD];
    const int tid = threadIdx.x;
    const int tx = tid & 15;
    const int ty = tid >> 4;
    const int row0 = blockIdx.y * BM;   // t
    const int col0 = blockIdx.x * BN;   // r

    const int lr = tid >> 1;            // 0..127 (tile row for loads)
    const int lc = (tid & 1) * 16;      // 0 or 16 (k offset for loads)
    const __half* aptr = g_hseq + (size_t)(row0 + lr) * H2 + lc;
    const float*  bptr = B      + (size_t)(col0 + lr) * H2 + lc;

    float acc[8][8];
#pragma unroll
    for (int i = 0; i < 8; i++)
#pragma unroll
        for (int j = 0; j < 8; j++) acc[i][j] = 0.0f;

    for (int k0 = 0; k0 < H2; k0 += BK) {
        uint4 a0 = *(const uint4*)(aptr + k0);
        uint4 a1 = *(const uint4*)(aptr + k0 + 8);
        float4 b0 = *(const float4*)(bptr + k0);
        float4 b1 = *(const float4*)(bptr + k0 + 4);
        float4 b2 = *(const float4*)(bptr + k0 + 8);
        float4 b3 = *(const float4*)(bptr + k0 + 12);
        __syncthreads();
        {
            unsigned aw[8] = {a0.x, a0.y, a0.z, a0.w, a1.x, a1.y, a1.z, a1.w};
#pragma unroll
            for (int e = 0; e < 8; e++) {
                float2 f = h2_to_f2(aw[e]);
                As[lc + 2 * e][lr]     = f.x;
                As[lc + 2 * e + 1][lr] = f.y;
            }
            float bw[16] = {b0.x, b0.y, b0.z, b0.w, b1.x, b1.y, b1.z, b1.w,
                            b2.x, b2.y, b2.z, b2.w, b3.x, b3.y, b3.z, b3.w};
#pragma unroll
            for (int e = 0; e < 16; e++) Bs[lc + e][lr] = bw[e];
        }
        __syncthreads();
#pragma unroll
        for (int k = 0; k < BK; k++) {
            float4 xa = *(const float4*)&As[k][ty * 8];
            float4 xb = *(const float4*)&As[k][ty * 8 + 4];
            float4 ya = *(const float4*)&Bs[k][tx * 8];
            float4 yb = *(const float4*)&Bs[k][tx * 8 + 4];
            float av[8] = {xa.x, xa.y, xa.z, xa.w, xb.x, xb.y, xb.z, xb.w};
            float bv[8] = {ya.x, ya.y, ya.z, ya.w, yb.x, yb.y, yb.z, yb.w};
#pragma unroll
            for (int i = 0; i < 8; i++)
#pragma unroll
                for (int j = 0; j < 8; j++) acc[i][j] = fmaf(av[i], bv[j], acc[i][j]);
        }
    }

    float bias[8];
#pragma unroll
    for (int j = 0; j < 8; j++) {
        int c = col0 + tx * 8 + j;
        bias[j] = __ldg(bih + c) + __ldg(bhh + c);
    }
#pragma unroll
    for (int i = 0; i < 8; i++) {
        float* crow = g_xw + (size_t)(row0 + ty * 8 + i) * NG + col0 + tx * 8;
        float4 v0 = {acc[i][0] + bias[0], acc[i][1] + bias[1], acc[i][2] + bias[2], acc[i][3] + bias[3]};
        float4 v1 = {acc[i][4] + bias[4], acc[i][5] + bias[5], acc[i][6] + bias[6], acc[i][7] + bias[7]};
        *(float4*)crow = v0;
        *(float4*)(crow + 4) = v1;
    }
}

// ---------------- persistent LSTM scan (v4: 1024 thr, K-quarter, staged h, 55+1 rows) ----
// 32 warps: warp = grp + 8*kq. Warp (grp,kq) computes rows [7*grp, 7*grp+7)
// over K-quarter kq. Row 55 (grp==7, rr==6) comes from g_wext via L1-cached
// global loads (CTA-private, resident in L1 after step 0). h_{t-1} staged into
// SMEM once per CTA (256 ld.cg.v4) to kill the L2 line-request burst.
__global__ __launch_bounds__(SCAN_THREADS, 1) void lstm_scan(const float* __restrict__ whh,
                                                             int layer) {
    extern __shared__ __align__(16) unsigned char smem_raw[];
    __half2* wsh = (__half2*)smem_raw;          // SMEM_ROWS x 1024 half2
    __shared__ __align__(16) uint4 h_s[256];    // staged h_{t-1} (4KB)
    __shared__ float gpart[4][ROWS];
    __shared__ float cst[JJ];

    const int tid  = threadIdx.x;
    const int lane = tid & 31;
    const int warp = tid >> 5;
    const int grp  = warp & 7;
    const int kq   = warp >> 3;                 // 0..3
    const int koff = kq * 64;                   // uint4 offset into a 256-uint4 row
    const int j0   = blockIdx.x * JJ;
    const int nj   = (H2 - j0 < JJ) ? (H2 - j0) : JJ;
    const int last_layer = (layer == LAYERS - 1);

    unsigned my_gen = 0;
    if (tid == 0) my_gen = ld_cg_u32(&g_bar_gen);

    // load + convert this CTA's first 55 weight rows into SMEM (row r = gate*JJ + jl)
    for (int r = warp; r < SMEM_ROWS; r += 32) {
        int gate = r / JJ;
        int jl = r - gate * JJ;
        __half2* dst = wsh + r * (H2 / 2);
        if (jl < nj) {
            const float2* src = (const float2*)(whh + ((size_t)gate * H2 + j0 + jl) * H2);
            for (int p = lane; p < H2 / 2; p += 32) {
                float2 v = __ldg(src + p);
                dst[p] = __floats2half2_rn(v.x, v.y);
            }
        } else {
            for (int p = lane; p < H2 / 2; p += 32) dst[p] = __half2half2(__float2half(0.0f));
        }
    }
    if (tid < JJ) cst[tid] = 0.0f;
    __syncthreads();

    const uint4* wbase = (const uint4*)smem_raw;
    const uint4* wext  = (const uint4*)(g_wext + ((size_t)layer * NCTA + blockIdx.x) * H2);

    for (int t = 0; t < T_STEPS; ++t) {
        // stage h_{t-1} into SMEM: one 16B .cg load per 16B per CTA (256 threads)
        if (tid < 256) {
            h_s[tid] = ldcg_v4(((const uint4*)(&g_hbuf[t & 1][0])) + tid);
        }
        // prefetch xw for this CTA's gate entries (warp 0 lanes; used in combine)
        float xwi = 0.f, xwf = 0.f, xwg = 0.f, xwo = 0.f;
        if (tid < nj) {
            const float* xwt = g_xw + (size_t)t * NG + j0 + tid;
            xwi = __ldg(xwt);
            xwf = __ldg(xwt + H2);
            xwg = __ldg(xwt + 2 * H2);
            xwo = __ldg(xwt + 3 * H2);
        }
        __syncthreads();   // h_s ready

        // this warp's K-quarter of h: 8 half2 regs (broadcast across same-kq warps)
        uint4 hu0 = h_s[koff + lane];
        uint4 hu1 = h_s[koff + lane + 32];
        __half2 hh[8];
        hh[0]=u2h2(hu0.x); hh[1]=u2h2(hu0.y); hh[2]=u2h2(hu0.z); hh[3]=u2h2(hu0.w);
        hh[4]=u2h2(hu1.x); hh[5]=u2h2(hu1.y); hh[6]=u2h2(hu1.z); hh[7]=u2h2(hu1.w);

        // 7 dot-product rows per warp, over this warp's K-quarter
#pragma unroll
        for (int rr = 0; rr < 7; rr++) {
            int r = grp * 7 + rr;
            const uint4* wr = (rr == 6 && grp == 7) ? (wext + koff)
                                                    : (wbase + (size_t)r * 256 + koff);
            uint4 wv0 = wr[lane];
            uint4 wv1 = wr[lane + 32];
            __half2 zero = __half2half2(__float2half(0.0f));
            __half2 a0 = zero, a1 = zero, a2 = zero, a3 = zero;
            a0 = __hfma2(u2h2(wv0.x), hh[0], a0);
            a1 = __hfma2(u2h2(wv0.y), hh[1], a1);
            a2 = __hfma2(u2h2(wv0.z), hh[2], a2);
            a3 = __hfma2(u2h2(wv0.w), hh[3], a3);
            a0 = __hfma2(u2h2(wv1.x), hh[4], a0);
            a1 = __hfma2(u2h2(wv1.y), hh[5], a1);
            a2 = __hfma2(u2h2(wv1.z), hh[6], a2);
            a3 = __hfma2(u2h2(wv1.w), hh[7], a3);
            __half2 s01 = __hadd2(a0, a1);      // each half: 4 products
            __half2 s23 = __hadd2(a2, a3);
            float2 f0 = __half22float2(s01);
            float2 f1 = __half22float2(s23);
            float a = (f0.x + f0.y) + (f1.x + f1.y);
#pragma unroll
            for (int o = 16; o; o >>= 1) a += __shfl_xor_sync(0xffffffffu, a, o);
            if (lane == 0) gpart[kq][r] = a;
        }
        __syncthreads();

        // gate combine + publish (warp 0 only), then grid barrier by thread 0
        if (warp == 0) {
            if (lane < nj) {
                int jl = lane;
                float gi = (gpart[0][0*JJ+jl] + gpart[1][0*JJ+jl]) + (gpart[2][0*JJ+jl] + gpart[3][0*JJ+jl]) + xwi;
                float gf = (gpart[0][1*JJ+jl] + gpart[1][1*JJ+jl]) + (gpart[2][1*JJ+jl] + gpart[3][1*JJ+jl]) + xwf;
                float gg = (gpart[0][2*JJ+jl] + gpart[1][2*JJ+jl]) + (gpart[2][2*JJ+jl] + gpart[3][2*JJ+jl]) + xwg;
                float go = (gpart[0][3*JJ+jl] + gpart[1][3*JJ+jl]) + (gpart[2][3*JJ+jl] + gpart[3][3*JJ+jl]) + xwo;
                float c = sigmoidf_fast(gf) * cst[jl] + sigmoidf_fast(gi) * tanhf_fast(gg);
                float h = sigmoidf_fast(go) * tanhf_fast(c);
                cst[jl] = c;
                int j = j0 + jl;
                __half hhv = __float2half_rn(h);
                g_hbuf[(t + 1) & 1][j] = hhv;                 // for next step's matvec
                g_hseq[(size_t)t * H2 + j] = hhv;             // for next layer's GEMM
                if (last_layer && t == T_STEPS - 1) g_hlast[j] = h;
            }
            __syncwarp();
            if (lane == 0) {
                __threadfence();                              // release h writes
                grid_bar(my_gen, gridDim.x);
            }
        }
        __syncthreads();
    }
}

// ---------------- final projection + log_softmax ----------------
__global__ void final_kernel(const float* __restrict__ wout, const float* __restrict__ bout,
                             float* __restrict__ out) {
    int tid = threadIdx.x;
    float s0 = 0.f, s1 = 0.f;
    for (int k = tid; k < H2; k += 256) {
        float h = g_hlast[k];
        s0 = fmaf(h, wout[k], s0);
        s1 = fmaf(h, wout[H2 + k], s1);
    }
    __shared__ float r0[8], r1[8];
#pragma unroll
    for (int o = 16; o; o >>= 1) {
        s0 += __shfl_xor_sync(0xffffffffu, s0, o);
        s1 += __shfl_xor_sync(0xffffffffu, s1, o);
    }
    if ((tid & 31) == 0) { r0[tid >> 5] = s0; r1[tid >> 5] = s1; }
    __syncthreads();
    if (tid == 0) {
        float l0 = bout[0], l1 = bout[1];
        for (int w = 0; w < 8; w++) { l0 += r0[w]; l1 += r1[w]; }
        float m = fmaxf(l0, l1);
        float z = expf(l0 - m) + expf(l1 - m);
        float lse = m + logf(z);
        out[0] = l0 - lse;
        out[1] = l1 - lse;
    }
}

// ---------------- launcher ----------------
extern "C" void kernel_launch(void* const* d_in, const int* in_sizes, int n_in,
                              void* d_out, int out_size) {
    const float* event = (const float*)d_in[0];
    const float* w_ih0 = (const float*)d_in[1];   // (8192, 1)
    const float* w_ih  = (const float*)d_in[2];   // (3, 8192, 2048)
    const float* w_hh  = (const float*)d_in[3];   // (4, 8192, 2048)
    const float* b_ih  = (const float*)d_in[4];   // (4, 8192)
    const float* b_hh  = (const float*)d_in[5];   // (4, 8192)
    const float* w_out = (const float*)d_in[6];   // (2, 2048)
    const float* b_out = (const float*)d_in[7];   // (2,)
    float* out = (float*)d_out;

    cudaFuncSetAttribute(lstm_scan, cudaFuncAttributeMaxDynamicSharedMemorySize, SCAN_SMEM);

    void* hbuf_ptr = nullptr;
    cudaGetSymbolAddress(&hbuf_ptr, g_hbuf);

    // pack the per-CTA extra weight rows (fp16) for all layers
    pack_extra<<<dim3(NCTA, LAYERS), 256>>>(w_hh);

    for (int l = 0; l < LAYERS; ++l) {
        if (l == 0) {
            dim3 grid(NG / (256 * 4), T_STEPS);
            xw0_kernel<<<grid, 256>>>(event, w_ih0, b_ih, b_hh);
        } else {
            dim3 grid(NG / BN, T_STEPS / BM);
            gemm_xw<<<grid, 256>>>(w_ih + (size_t)(l - 1) * NG * H2,
                                   b_ih + (size_t)l * NG,
                                   b_hh + (size_t)l * NG);
        }
        cudaMemsetAsync(hbuf_ptr, 0, 2 * H2 * sizeof(__half));
        lstm_scan<<<NCTA, SCAN_THREADS, SCAN_SMEM>>>(w_hh + (size_t)l * NG * H2, l);
    }
    final_kernel<<<1, 256>>>(w_out, b_out, out);
}

// round 11
// speedup vs baseline: 1.0551x; 1.0015x over previous
#include <cuda_runtime.h>
#include <cuda_fp16.h>
#include <math.h>

#define H2 2048
#define T_STEPS 2048
#define NG 8192            // 4*H2
#define LAYERS 4
#define JJ 14              // h-elements per CTA
#define ROWS 56            // 4*JJ gate rows per CTA
#define NCTA 147           // ceil(2048/14)
#define SCAN_THREADS 1024
#define SMEM_ROWS 55                      // rows kept in SMEM (row 55 streamed via L1)
#define SCAN_SMEM (SMEM_ROWS * H2 * 2)    // 225280 bytes of fp16 weights

// ---------------- scratch (static device globals; no allocation) ----------------
__device__ float  g_xw[(size_t)T_STEPS * NG];        // 67 MB: xw for current layer
__device__ __align__(16) __half g_hseq[(size_t)T_STEPS * H2]; // h sequence (fp16)
__device__ __align__(16) __half g_hbuf[2][H2];       // double-buffered h for the scan
__device__ __align__(16) __half g_wext[(size_t)LAYERS * NCTA * H2]; // per-CTA extra row (fp16)
__device__ float  g_hlast[H2];                       // fp32 h at t=T-1
__device__ unsigned g_bar_count = 0;
__device__ unsigned g_bar_gen   = 0;

// ---------------- helpers ----------------
static __device__ __forceinline__ float2 h2_to_f2(unsigned u) {
    __half2 h;
    *reinterpret_cast<unsigned*>(&h) = u;
    return __half22float2(h);
}
static __device__ __forceinline__ __half2 u2h2(unsigned u) {
    __half2 h;
    *reinterpret_cast<unsigned*>(&h) = u;
    return h;
}
static __device__ __forceinline__ uint4 ldcg_v4(const uint4* p) {
    uint4 v;
    asm volatile("ld.global.cg.v4.u32 {%0,%1,%2,%3}, [%4];"
                 : "=r"(v.x), "=r"(v.y), "=r"(v.z), "=r"(v.w) : "l"(p));
    return v;
}
static __device__ __forceinline__ unsigned ld_cg_u32(const unsigned* p) {
    unsigned v;
    asm volatile("ld.global.cg.u32 %0, [%1];" : "=r"(v) : "l"(p));
    return v;
}
static __device__ __forceinline__ float sigmoidf_fast(float x) {
    return 1.0f / (1.0f + __expf(-x));
}
static __device__ __forceinline__ float tanhf_fast(float x) {
    return 2.0f / (1.0f + __expf(-2.0f * x)) - 1.0f;
}

// flat grid barrier (thread 0 of each CTA): atomic arrivals to one counter,
// non-atomic .cg poll of the generation word. Bounded spin (16 rounds, single
// L2 line -> negligible traffic) before falling back to nanosleep, so early
// arrivals discover the release at load latency, not sleep-quantum granularity.
// Self-resetting; graph-replay safe.
static __device__ __forceinline__ void grid_bar(unsigned& my_gen, unsigned nct) {
    my_gen += 1;
    unsigned old = atomicAdd(&g_bar_count, 1);
    if (old == nct - 1) {
        atomicExch(&g_bar_count, 0);
        __threadfence();
        atomicAdd(&g_bar_gen, 1);               // release
    }
    int spin = 0;
    while ((int)(ld_cg_u32(&g_bar_gen) - my_gen) < 0) {
        if (++spin > 16) __nanosleep(64);
    }
    __threadfence();                            // acquire
}

// ---------------- pack per-CTA extra weight row (gate o, jl=13) to fp16 ----------------
__global__ void pack_extra(const float* __restrict__ whh) {
    int k = blockIdx.x;          // CTA index
    int l = blockIdx.y;          // layer
    int j = JJ * k + JJ - 1;     // h index of the extra row
    __half* dst = g_wext + ((size_t)l * NCTA + k) * H2;
    if (j >= H2) {
        for (int i = threadIdx.x; i < H2; i += 256) dst[i] = __float2half(0.0f);
        return;
    }
    const float* src = whh + ((size_t)l * NG + 3 * H2 + j) * H2;
    for (int i = threadIdx.x; i < H2; i += 256) dst[i] = __float2half_rn(src[i]);
}

// ---------------- layer-0 xw: xw[t][r] = event[t]*w_ih0[r] + b_ih[r] + b_hh[r] ----------------
__global__ void xw0_kernel(const float* __restrict__ event, const float* __restrict__ w0,
                           const float* __restrict__ bih, const float* __restrict__ bhh) {
    int t = blockIdx.y;
    int c = (blockIdx.x * blockDim.x + threadIdx.x) * 4;
    float e = event[t];
    float4 w  = *(const float4*)(w0 + c);
    float4 bi = *(const float4*)(bih + c);
    float4 bh = *(const float4*)(bhh + c);
    float4 r;
    r.x = fmaf(e, w.x, bi.x + bh.x);
    r.y = fmaf(e, w.y, bi.y + bh.y);
    r.z = fmaf(e, w.z, bi.z + bh.z);
    r.w = fmaf(e, w.w, bi.w + bh.w);
    *(float4*)(g_xw + (size_t)t * NG + c) = r;
}

// ---------------- xw GEMM: g_xw[t][r] = sum_k g_hseq[t][k] * B[r][k] + bias[r] ----------------
#define BM 128
#define BN 128
#define BK 32
#define SPAD 4

__global__ __launch_bounds__(256, 2) void gemm_xw(const float* __restrict__ B,
                                                  const float* __restrict__ bih,
                                                  const float* __restrict__ bhh) {
    __shared__ float As[BK][BM + SPAD];
    __shared__ float Bs[BK][BN + SPAD];
    const int tid = threadIdx.x;
    const int tx = tid & 15;
    const int ty = tid >> 4;
    const int row0 = blockIdx.y * BM;   // t
    const int col0 = blockIdx.x * BN;   // r

    const int lr = tid >> 1;            // 0..127 (tile row for loads)
    const int lc = (tid & 1) * 16;      // 0 or 16 (k offset for loads)
    const __half* aptr = g_hseq + (size_t)(row0 + lr) * H2 + lc;
    const float*  bptr = B      + (size_t)(col0 + lr) * H2 + lc;

    float acc[8][8];
#pragma unroll
    for (int i = 0; i < 8; i++)
#pragma unroll
        for (int j = 0; j < 8; j++) acc[i][j] = 0.0f;

    for (int k0 = 0; k0 < H2; k0 += BK) {
        uint4 a0 = *(const uint4*)(aptr + k0);
        uint4 a1 = *(const uint4*)(aptr + k0 + 8);
        float4 b0 = *(const float4*)(bptr + k0);
        float4 b1 = *(const float4*)(bptr + k0 + 4);
        float4 b2 = *(const float4*)(bptr + k0 + 8);
        float4 b3 = *(const float4*)(bptr + k0 + 12);
        __syncthreads();
        {
            unsigned aw[8] = {a0.x, a0.y, a0.z, a0.w, a1.x, a1.y, a1.z, a1.w};
#pragma unroll
            for (int e = 0; e < 8; e++) {
                float2 f = h2_to_f2(aw[e]);
                As[lc + 2 * e][lr]     = f.x;
                As[lc + 2 * e + 1][lr] = f.y;
            }
            float bw[16] = {b0.x, b0.y, b0.z, b0.w, b1.x, b1.y, b1.z, b1.w,
                            b2.x, b2.y, b2.z, b2.w, b3.x, b3.y, b3.z, b3.w};
#pragma unroll
            for (int e = 0; e < 16; e++) Bs[lc + e][lr] = bw[e];
        }
        __syncthreads();
#pragma unroll
        for (int k = 0; k < BK; k++) {
            float4 xa = *(const float4*)&As[k][ty * 8];
            float4 xb = *(const float4*)&As[k][ty * 8 + 4];
            float4 ya = *(const float4*)&Bs[k][tx * 8];
            float4 yb = *(const float4*)&Bs[k][tx * 8 + 4];
            float av[8] = {xa.x, xa.y, xa.z, xa.w, xb.x, xb.y, xb.z, xb.w};
            float bv[8] = {ya.x, ya.y, ya.z, ya.w, yb.x, yb.y, yb.z, yb.w};
#pragma unroll
            for (int i = 0; i < 8; i++)
#pragma unroll
                for (int j = 0; j < 8; j++) acc[i][j] = fmaf(av[i], bv[j], acc[i][j]);
        }
    }

    float bias[8];
#pragma unroll
    for (int j = 0; j < 8; j++) {
        int c = col0 + tx * 8 + j;
        bias[j] = __ldg(bih + c) + __ldg(bhh + c);
    }
#pragma unroll
    for (int i = 0; i < 8; i++) {
        float* crow = g_xw + (size_t)(row0 + ty * 8 + i) * NG + col0 + tx * 8;
        float4 v0 = {acc[i][0] + bias[0], acc[i][1] + bias[1], acc[i][2] + bias[2], acc[i][3] + bias[3]};
        float4 v1 = {acc[i][4] + bias[4], acc[i][5] + bias[5], acc[i][6] + bias[6], acc[i][7] + bias[7]};
        *(float4*)crow = v0;
        *(float4*)(crow + 4) = v1;
    }
}

// ---------------- persistent LSTM scan (v4 core + hybrid-spin barrier) ----------
// 32 warps: warp = grp + 8*kq. Warp (grp,kq) computes rows [7*grp, 7*grp+7)
// over K-quarter kq. Row 55 (grp==7, rr==6) comes from g_wext via L1-cached
// global loads. h_{t-1} staged into SMEM once per CTA (256 ld.cg.v4).
__global__ __launch_bounds__(SCAN_THREADS, 1) void lstm_scan(const float* __restrict__ whh,
                                                             int layer) {
    extern __shared__ __align__(16) unsigned char smem_raw[];
    __half2* wsh = (__half2*)smem_raw;          // SMEM_ROWS x 1024 half2
    __shared__ __align__(16) uint4 h_s[256];    // staged h_{t-1} (4KB)
    __shared__ float gpart[4][ROWS];
    __shared__ float cst[JJ];

    const int tid  = threadIdx.x;
    const int lane = tid & 31;
    const int warp = tid >> 5;
    const int grp  = warp & 7;
    const int kq   = warp >> 3;                 // 0..3
    const int koff = kq * 64;                   // uint4 offset into a 256-uint4 row
    const int j0   = blockIdx.x * JJ;
    const int nj   = (H2 - j0 < JJ) ? (H2 - j0) : JJ;
    const int last_layer = (layer == LAYERS - 1);

    unsigned my_gen = 0;
    if (tid == 0) my_gen = ld_cg_u32(&g_bar_gen);

    // load + convert this CTA's first 55 weight rows into SMEM (row r = gate*JJ + jl)
    for (int r = warp; r < SMEM_ROWS; r += 32) {
        int gate = r / JJ;
        int jl = r - gate * JJ;
        __half2* dst = wsh + r * (H2 / 2);
        if (jl < nj) {
            const float2* src = (const float2*)(whh + ((size_t)gate * H2 + j0 + jl) * H2);
            for (int p = lane; p < H2 / 2; p += 32) {
                float2 v = __ldg(src + p);
                dst[p] = __floats2half2_rn(v.x, v.y);
            }
        } else {
            for (int p = lane; p < H2 / 2; p += 32) dst[p] = __half2half2(__float2half(0.0f));
        }
    }
    if (tid < JJ) cst[tid] = 0.0f;
    __syncthreads();

    const uint4* wbase = (const uint4*)smem_raw;
    const uint4* wext  = (const uint4*)(g_wext + ((size_t)layer * NCTA + blockIdx.x) * H2);

    for (int t = 0; t < T_STEPS; ++t) {
        // stage h_{t-1} into SMEM: one 16B .cg load per 16B per CTA (256 threads)
        if (tid < 256) {
            h_s[tid] = ldcg_v4(((const uint4*)(&g_hbuf[t & 1][0])) + tid);
        }
        // prefetch xw for this CTA's gate entries (warp 0 lanes; used in combine)
        float xwi = 0.f, xwf = 0.f, xwg = 0.f, xwo = 0.f;
        if (tid < nj) {
            const float* xwt = g_xw + (size_t)t * NG + j0 + tid;
            xwi = __ldg(xwt);
            xwf = __ldg(xwt + H2);
            xwg = __ldg(xwt + 2 * H2);
            xwo = __ldg(xwt + 3 * H2);
        }
        __syncthreads();   // h_s ready

        // this warp's K-quarter of h: 8 half2 regs (broadcast across same-kq warps)
        uint4 hu0 = h_s[koff + lane];
        uint4 hu1 = h_s[koff + lane + 32];
        __half2 hh[8];
        hh[0]=u2h2(hu0.x); hh[1]=u2h2(hu0.y); hh[2]=u2h2(hu0.z); hh[3]=u2h2(hu0.w);
        hh[4]=u2h2(hu1.x); hh[5]=u2h2(hu1.y); hh[6]=u2h2(hu1.z); hh[7]=u2h2(hu1.w);

        // 7 dot-product rows per warp, over this warp's K-quarter
#pragma unroll
        for (int rr = 0; rr < 7; rr++) {
            int r = grp * 7 + rr;
            const uint4* wr = (rr == 6 && grp == 7) ? (wext + koff)
                                                    : (wbase + (size_t)r * 256 + koff);
            uint4 wv0 = wr[lane];
            uint4 wv1 = wr[lane + 32];
            __half2 zero = __half2half2(__float2half(0.0f));
            __half2 a0 = zero, a1 = zero, a2 = zero, a3 = zero;
            a0 = __hfma2(u2h2(wv0.x), hh[0], a0);
            a1 = __hfma2(u2h2(wv0.y), hh[1], a1);
            a2 = __hfma2(u2h2(wv0.z), hh[2], a2);
            a3 = __hfma2(u2h2(wv0.w), hh[3], a3);
            a0 = __hfma2(u2h2(wv1.x), hh[4], a0);
            a1 = __hfma2(u2h2(wv1.y), hh[5], a1);
            a2 = __hfma2(u2h2(wv1.z), hh[6], a2);
            a3 = __hfma2(u2h2(wv1.w), hh[7], a3);
            __half2 s01 = __hadd2(a0, a1);      // each half: 4 products
            __half2 s23 = __hadd2(a2, a3);
            float2 f0 = __half22float2(s01);
            float2 f1 = __half22float2(s23);
            float a = (f0.x + f0.y) + (f1.x + f1.y);
#pragma unroll
            for (int o = 16; o; o >>= 1) a += __shfl_xor_sync(0xffffffffu, a, o);
            if (lane == 0) gpart[kq][r] = a;
        }
        __syncthreads();

        // gate combine + publish (warp 0 only), then grid barrier by thread 0
        if (warp == 0) {
            if (lane < nj) {
                int jl = lane;
                float gi = (gpart[0][0*JJ+jl] + gpart[1][0*JJ+jl]) + (gpart[2][0*JJ+jl] + gpart[3][0*JJ+jl]) + xwi;
                float gf = (gpart[0][1*JJ+jl] + gpart[1][1*JJ+jl]) + (gpart[2][1*JJ+jl] + gpart[3][1*JJ+jl]) + xwf;
                float gg = (gpart[0][2*JJ+jl] + gpart[1][2*JJ+jl]) + (gpart[2][2*JJ+jl] + gpart[3][2*JJ+jl]) + xwg;
                float go = (gpart[0][3*JJ+jl] + gpart[1][3*JJ+jl]) + (gpart[2][3*JJ+jl] + gpart[3][3*JJ+jl]) + xwo;
                float c = sigmoidf_fast(gf) * cst[jl] + sigmoidf_fast(gi) * tanhf_fast(gg);
                float h = sigmoidf_fast(go) * tanhf_fast(c);
                cst[jl] = c;
                int j = j0 + jl;
                __half hhv = __float2half_rn(h);
                g_hbuf[(t + 1) & 1][j] = hhv;                 // for next step's matvec
                g_hseq[(size_t)t * H2 + j] = hhv;             // for next layer's GEMM
                if (last_layer && t == T_STEPS - 1) g_hlast[j] = h;
            }
            __syncwarp();
            if (lane == 0) {
                __threadfence();                              // release h writes
                grid_bar(my_gen, gridDim.x);
            }
        }
        __syncthreads();
    }
}

// ---------------- final projection + log_softmax ----------------
__global__ void final_kernel(const float* __restrict__ wout, const float* __restrict__ bout,
                             float* __restrict__ out) {
    int tid = threadIdx.x;
    float s0 = 0.f, s1 = 0.f;
    for (int k = tid; k < H2; k += 256) {
        float h = g_hlast[k];
        s0 = fmaf(h, wout[k], s0);
        s1 = fmaf(h, wout[H2 + k], s1);
    }
    __shared__ float r0[8], r1[8];
#pragma unroll
    for (int o = 16; o; o >>= 1) {
        s0 += __shfl_xor_sync(0xffffffffu, s0, o);
        s1 += __shfl_xor_sync(0xffffffffu, s1, o);
    }
    if ((tid & 31) == 0) { r0[tid >> 5] = s0; r1[tid >> 5] = s1; }
    __syncthreads();
    if (tid == 0) {
        float l0 = bout[0], l1 = bout[1];
        for (int w = 0; w < 8; w++) { l0 += r0[w]; l1 += r1[w]; }
        float m = fmaxf(l0, l1);
        float z = expf(l0 - m) + expf(l1 - m);
        float lse = m + logf(z);
        out[0] = l0 - lse;
        out[1] = l1 - lse;
    }
}

// ---------------- launcher ----------------
extern "C" void kernel_launch(void* const* d_in, const int* in_sizes, int n_in,
                              void* d_out, int out_size) {
    const float* event = (const float*)d_in[0];
    const float* w_ih0 = (const float*)d_in[1];   // (8192, 1)
    const float* w_ih  = (const float*)d_in[2];   // (3, 8192, 2048)
    const float* w_hh  = (const float*)d_in[3];   // (4, 8192, 2048)
    const float* b_ih  = (const float*)d_in[4];   // (4, 8192)
    const float* b_hh  = (const float*)d_in[5];   // (4, 8192)
    const float* w_out = (const float*)d_in[6];   // (2, 2048)
    const float* b_out = (const float*)d_in[7];   // (2,)
    float* out = (float*)d_out;

    cudaFuncSetAttribute(lstm_scan, cudaFuncAttributeMaxDynamicSharedMemorySize, SCAN_SMEM);

    void* hbuf_ptr = nullptr;
    cudaGetSymbolAddress(&hbuf_ptr, g_hbuf);

    // pack the per-CTA extra weight rows (fp16) for all layers
    pack_extra<<<dim3(NCTA, LAYERS), 256>>>(w_hh);

    for (int l = 0; l < LAYERS; ++l) {
        if (l == 0) {
            dim3 grid(NG / (256 * 4), T_STEPS);
            xw0_kernel<<<grid, 256>>>(event, w_ih0, b_ih, b_hh);
        } else {
            dim3 grid(NG / BN, T_STEPS / BM);
            gemm_xw<<<grid, 256>>>(w_ih + (size_t)(l - 1) * NG * H2,
                                   b_ih + (size_t)l * NG,
                                   b_hh + (size_t)l * NG);
        }
        cudaMemsetAsync(hbuf_ptr, 0, 2 * H2 * sizeof(__half));
        lstm_scan<<<NCTA, SCAN_THREADS, SCAN_SMEM>>>(w_hh + (size_t)l * NG * H2, l);
    }
    final_kernel<<<1, 256>>>(w_out, b_out, out);
}

// round 12
// speedup vs baseline: 1.1592x; 1.0986x over previous
#include <cuda_runtime.h>
#include <cuda_fp16.h>
#include <math.h>

#define H2 2048
#define T_STEPS 2048
#define NG 8192            // 4*H2
#define LAYERS 4
#define JJ 14              // h-elements per CTA
#define ROWS 56            // 4*JJ gate rows per CTA
#define NCTA 147           // ceil(2048/14)
#define SCAN_THREADS 1024
#define SMEM_ROWS 55                      // rows kept in SMEM (row 55 streamed via L1)
#define SCAN_SMEM (SMEM_ROWS * H2 * 2)    // 225280 bytes of fp16 weights

// ---------------- scratch (static device globals; no allocation) ----------------
__device__ float  g_xw[(size_t)T_STEPS * NG];        // 67 MB: xw for current layer
__device__ __align__(16) __half g_hseq[(size_t)T_STEPS * H2]; // h sequence (fp16)
__device__ __align__(16) __half g_hbuf[2][H2];       // double-buffered h for the scan
__device__ __align__(16) __half g_wext[(size_t)LAYERS * NCTA * H2]; // per-CTA extra row (fp16)
__device__ float  g_hlast[H2];                       // fp32 h at t=T-1
// barrier state: two parity counters (128B apart) + generation word.
// Counters are reset by CTA0 each phase (end each launch at 0); gen is
// monotone across launches/replays -> graph-replay safe.
__device__ unsigned g_cnt[2 * 32];
__device__ unsigned g_gen2 = 0;

// ---------------- helpers ----------------
static __device__ __forceinline__ float2 h2_to_f2(unsigned u) {
    __half2 h;
    *reinterpret_cast<unsigned*>(&h) = u;
    return __half22float2(h);
}
static __device__ __forceinline__ __half2 u2h2(unsigned u) {
    __half2 h;
    *reinterpret_cast<unsigned*>(&h) = u;
    return h;
}
static __device__ __forceinline__ uint4 ldcg_v4(const uint4* p) {
    uint4 v;
    asm volatile("ld.global.cg.v4.u32 {%0,%1,%2,%3}, [%4];"
                 : "=r"(v.x), "=r"(v.y), "=r"(v.z), "=r"(v.w) : "l"(p));
    return v;
}
static __device__ __forceinline__ unsigned ld_cg_u32(const unsigned* p) {
    unsigned v;
    asm volatile("ld.global.cg.u32 %0, [%1];" : "=r"(v) : "l"(p));
    return v;
}
// scoped memory-model ops: no full MEMBAR anywhere in the sync path
static __device__ __forceinline__ void red_add_release(unsigned* p) {
    asm volatile("red.release.gpu.global.add.u32 [%0], 1;" :: "l"(p) : "memory");
}
static __device__ __forceinline__ unsigned ld_acq(const unsigned* p) {
    unsigned v;
    asm volatile("ld.acquire.gpu.global.u32 %0, [%1];" : "=r"(v) : "l"(p) : "memory");
    return v;
}
static __device__ __forceinline__ void st_rel(unsigned* p, unsigned v) {
    asm volatile("st.release.gpu.global.u32 [%0], %1;" :: "l"(p), "r"(v) : "memory");
}
static __device__ __forceinline__ void st_rlx(unsigned* p, unsigned v) {
    asm volatile("st.relaxed.gpu.global.u32 [%0], %1;" :: "l"(p), "r"(v) : "memory");
}
static __device__ __forceinline__ float sigmoidf_fast(float x) {
    return 1.0f / (1.0f + __expf(-x));
}
static __device__ __forceinline__ float tanhf_fast(float x) {
    return 2.0f / (1.0f + __expf(-2.0f * x)) - 1.0f;
}

// grid barrier, called by thread 0 of each CTA for phase ph (1,2,3,...):
//  - every CTA: fire-and-forget release-arrive on counter[ph&1] (no return wait)
//  - CTA0: acquire-poll the counter to NCTA, reset it, release gen = base+ph
//  - others: acquire-poll gen >= base+ph
// Counter reuse is race-free: counter p is next used at phase p+2, and any
// phase-p+2 arrival happens only after that CTA observed gen >= base+p+1,
// which CTA0 published strictly after resetting counter p.
static __device__ __forceinline__ void grid_sync(unsigned ph, unsigned base, bool cta0) {
    unsigned* cnt = &g_cnt[(ph & 1) * 32];
    red_add_release(cnt);
    if (cta0) {
        int spin = 0;
        while (ld_acq(cnt) < NCTA) { if (++spin > 64) __nanosleep(64); }
        st_rlx(cnt, 0);
        st_rel(&g_gen2, base + ph);
    } else {
        int spin = 0;
        while ((int)(ld_acq(&g_gen2) - (base + ph)) < 0) { if (++spin > 64) __nanosleep(64); }
    }
}

// ---------------- pack per-CTA extra weight row (gate o, jl=13) to fp16 ----------------
__global__ void pack_extra(const float* __restrict__ whh) {
    int k = blockIdx.x;          // CTA index
    int l = blockIdx.y;          // layer
    int j = JJ * k + JJ - 1;     // h index of the extra row
    __half* dst = g_wext + ((size_t)l * NCTA + k) * H2;
    if (j >= H2) {
        for (int i = threadIdx.x; i < H2; i += 256) dst[i] = __float2half(0.0f);
        return;
    }
    const float* src = whh + ((size_t)l * NG + 3 * H2 + j) * H2;
    for (int i = threadIdx.x; i < H2; i += 256) dst[i] = __float2half_rn(src[i]);
}

// ---------------- nop pad so lstm_scan(layer1) lands on ncu's -s 5 capture slot ----
__global__ void nop_kernel() {}

// ---------------- layer-0 xw: xw[t][r] = event[t]*w_ih0[r] + b_ih[r] + b_hh[r] ----------------
__global__ void xw0_kernel(const float* __restrict__ event, const float* __restrict__ w0,
                           const float* __restrict__ bih, const float* __restrict__ bhh) {
    int t = blockIdx.y;
    int c = (blockIdx.x * blockDim.x + threadIdx.x) * 4;
    float e = event[t];
    float4 w  = *(const float4*)(w0 + c);
    float4 bi = *(const float4*)(bih + c);
    float4 bh = *(const float4*)(bhh + c);
    float4 r;
    r.x = fmaf(e, w.x, bi.x + bh.x);
    r.y = fmaf(e, w.y, bi.y + bh.y);
    r.z = fmaf(e, w.z, bi.z + bh.z);
    r.w = fmaf(e, w.w, bi.w + bh.w);
    *(float4*)(g_xw + (size_t)t * NG + c) = r;
}

// ---------------- xw GEMM: g_xw[t][r] = sum_k g_hseq[t][k] * B[r][k] + bias[r] ----------------
#define BM 128
#define BN 128
#define BK 32
#define SPAD 4

__global__ __launch_bounds__(256, 2) void gemm_xw(const float* __restrict__ B,
                                                  const float* __restrict__ bih,
                                                  const float* __restrict__ bhh) {
    __shared__ float As[BK][BM + SPAD];
    __shared__ float Bs[BK][BN + SPAD];
    const int tid = threadIdx.x;
    const int tx = tid & 15;
    const int ty = tid >> 4;
    const int row0 = blockIdx.y * BM;   // t
    const int col0 = blockIdx.x * BN;   // r

    const int lr = tid >> 1;            // 0..127 (tile row for loads)
    const int lc = (tid & 1) * 16;      // 0 or 16 (k offset for loads)
    const __half* aptr = g_hseq + (size_t)(row0 + lr) * H2 + lc;
    const float*  bptr = B      + (size_t)(col0 + lr) * H2 + lc;

    float acc[8][8];
#pragma unroll
    for (int i = 0; i < 8; i++)
#pragma unroll
        for (int j = 0; j < 8; j++) acc[i][j] = 0.0f;

    for (int k0 = 0; k0 < H2; k0 += BK) {
        uint4 a0 = *(const uint4*)(aptr + k0);
        uint4 a1 = *(const uint4*)(aptr + k0 + 8);
        float4 b0 = *(const float4*)(bptr + k0);
        float4 b1 = *(const float4*)(bptr + k0 + 4);
        float4 b2 = *(const float4*)(bptr + k0 + 8);
        float4 b3 = *(const float4*)(bptr + k0 + 12);
        __syncthreads();
        {
            unsigned aw[8] = {a0.x, a0.y, a0.z, a0.w, a1.x, a1.y, a1.z, a1.w};
#pragma unroll
            for (int e = 0; e < 8; e++) {
                float2 f = h2_to_f2(aw[e]);
                As[lc + 2 * e][lr]     = f.x;
                As[lc + 2 * e + 1][lr] = f.y;
            }
            float bw[16] = {b0.x, b0.y, b0.z, b0.w, b1.x, b1.y, b1.z, b1.w,
                            b2.x, b2.y, b2.z, b2.w, b3.x, b3.y, b3.z, b3.w};
#pragma unroll
            for (int e = 0; e < 16; e++) Bs[lc + e][lr] = bw[e];
        }
        __syncthreads();
#pragma unroll
        for (int k = 0; k < BK; k++) {
            float4 xa = *(const float4*)&As[k][ty * 8];
            float4 xb = *(const float4*)&As[k][ty * 8 + 4];
            float4 ya = *(const float4*)&Bs[k][tx * 8];
            float4 yb = *(const float4*)&Bs[k][tx * 8 + 4];
            float av[8] = {xa.x, xa.y, xa.z, xa.w, xb.x, xb.y, xb.z, xb.w};
            float bv[8] = {ya.x, ya.y, ya.z, ya.w, yb.x, yb.y, yb.z, yb.w};
#pragma unroll
            for (int i = 0; i < 8; i++)
#pragma unroll
                for (int j = 0; j < 8; j++) acc[i][j] = fmaf(av[i], bv[j], acc[i][j]);
        }
    }

    float bias[8];
#pragma unroll
    for (int j = 0; j < 8; j++) {
        int c = col0 + tx * 8 + j;
        bias[j] = __ldg(bih + c) + __ldg(bhh + c);
    }
#pragma unroll
    for (int i = 0; i < 8; i++) {
        float* crow = g_xw + (size_t)(row0 + ty * 8 + i) * NG + col0 + tx * 8;
        float4 v0 = {acc[i][0] + bias[0], acc[i][1] + bias[1], acc[i][2] + bias[2], acc[i][3] + bias[3]};
        float4 v1 = {acc[i][4] + bias[4], acc[i][5] + bias[5], acc[i][6] + bias[6], acc[i][7] + bias[7]};
        *(float4*)crow = v0;
        *(float4*)(crow + 4) = v1;
    }
}

// ---------------- persistent LSTM scan (v4 core + scoped acq/rel barrier) ----------
// 32 warps: warp = grp + 8*kq. Warp (grp,kq) computes rows [7*grp, 7*grp+7)
// over K-quarter kq. Row 55 (grp==7, rr==6) from g_wext via L1-cached loads.
// h_{t-1} staged into SMEM once per CTA. Prologue zeroes this CTA's h slots
// (replaces the host-side memset) sealed by grid phase 1.
__global__ __launch_bounds__(SCAN_THREADS, 1) void lstm_scan(const float* __restrict__ whh,
                                                             int layer) {
    extern __shared__ __align__(16) unsigned char smem_raw[];
    __half2* wsh = (__half2*)smem_raw;          // SMEM_ROWS x 1024 half2
    __shared__ __align__(16) uint4 h_s[256];    // staged h_{t-1} (4KB)
    __shared__ float gpart[4][ROWS];
    __shared__ float cst[JJ];

    const int tid  = threadIdx.x;
    const int lane = tid & 31;
    const int warp = tid >> 5;
    const int grp  = warp & 7;
    const int kq   = warp >> 3;                 // 0..3
    const int koff = kq * 64;                   // uint4 offset into a 256-uint4 row
    const int j0   = blockIdx.x * JJ;
    const int nj   = (H2 - j0 < JJ) ? (H2 - j0) : JJ;
    const int last_layer = (layer == LAYERS - 1);
    const bool cta0 = (blockIdx.x == 0);

    unsigned base = 0, ph = 0;
    if (tid == 0) base = ld_cg_u32(&g_gen2);

    // zero this CTA's h slots in both scan buffers (replaces host memset)
    if (tid < JJ) {
        int j = j0 + tid;
        if (j < H2) {
            g_hbuf[0][j] = __float2half(0.0f);
            g_hbuf[1][j] = __float2half(0.0f);
        }
    }

    // load + convert this CTA's first 55 weight rows into SMEM (row r = gate*JJ + jl)
    for (int r = warp; r < SMEM_ROWS; r += 32) {
        int gate = r / JJ;
        int jl = r - gate * JJ;
        __half2* dst = wsh + r * (H2 / 2);
        if (jl < nj) {
            const float2* src = (const float2*)(whh + ((size_t)gate * H2 + j0 + jl) * H2);
            for (int p = lane; p < H2 / 2; p += 32) {
                float2 v = __ldg(src + p);
                dst[p] = __floats2half2_rn(v.x, v.y);
            }
        } else {
            for (int p = lane; p < H2 / 2; p += 32) dst[p] = __half2half2(__float2half(0.0f));
        }
    }
    if (tid < JJ) cst[tid] = 0.0f;
    __syncthreads();

    // phase 1: all CTAs' zeroed h slots visible grid-wide
    if (tid == 0) grid_sync(++ph, base, cta0);
    __syncthreads();

    const uint4* wbase = (const uint4*)smem_raw;
    const uint4* wext  = (const uint4*)(g_wext + ((size_t)layer * NCTA + blockIdx.x) * H2);

    for (int t = 0; t < T_STEPS; ++t) {
        // stage h_{t-1} into SMEM: one 16B .cg load per 16B per CTA (256 threads)
        if (tid < 256) {
            h_s[tid] = ldcg_v4(((const uint4*)(&g_hbuf[t & 1][0])) + tid);
        }
        // prefetch xw for this CTA's gate entries (warp 0 lanes; used in combine)
        float xwi = 0.f, xwf = 0.f, xwg = 0.f, xwo = 0.f;
        if (tid < nj) {
            const float* xwt = g_xw + (size_t)t * NG + j0 + tid;
            xwi = __ldg(xwt);
            xwf = __ldg(xwt + H2);
            xwg = __ldg(xwt + 2 * H2);
            xwo = __ldg(xwt + 3 * H2);
        }
        __syncthreads();   // h_s ready

        // this warp's K-quarter of h: 8 half2 regs (broadcast across same-kq warps)
        uint4 hu0 = h_s[koff + lane];
        uint4 hu1 = h_s[koff + lane + 32];
        __half2 hh[8];
        hh[0]=u2h2(hu0.x); hh[1]=u2h2(hu0.y); hh[2]=u2h2(hu0.z); hh[3]=u2h2(hu0.w);
        hh[4]=u2h2(hu1.x); hh[5]=u2h2(hu1.y); hh[6]=u2h2(hu1.z); hh[7]=u2h2(hu1.w);

        // 7 dot-product rows per warp, over this warp's K-quarter
#pragma unroll
        for (int rr = 0; rr < 7; rr++) {
            int r = grp * 7 + rr;
            const uint4* wr = (rr == 6 && grp == 7) ? (wext + koff)
                                                    : (wbase + (size_t)r * 256 + koff);
            uint4 wv0 = wr[lane];
            uint4 wv1 = wr[lane + 32];
            __half2 zero = __half2half2(__float2half(0.0f));
            __half2 a0 = zero, a1 = zero, a2 = zero, a3 = zero;
            a0 = __hfma2(u2h2(wv0.x), hh[0], a0);
            a1 = __hfma2(u2h2(wv0.y), hh[1], a1);
            a2 = __hfma2(u2h2(wv0.z), hh[2], a2);
            a3 = __hfma2(u2h2(wv0.w), hh[3], a3);
            a0 = __hfma2(u2h2(wv1.x), hh[4], a0);
            a1 = __hfma2(u2h2(wv1.y), hh[5], a1);
            a2 = __hfma2(u2h2(wv1.z), hh[6], a2);
            a3 = __hfma2(u2h2(wv1.w), hh[7], a3);
            __half2 s01 = __hadd2(a0, a1);      // each half: 4 products
            __half2 s23 = __hadd2(a2, a3);
            float2 f0 = __half22float2(s01);
            float2 f1 = __half22float2(s23);
            float a = (f0.x + f0.y) + (f1.x + f1.y);
#pragma unroll
            for (int o = 16; o; o >>= 1) a += __shfl_xor_sync(0xffffffffu, a, o);
            if (lane == 0) gpart[kq][r] = a;
        }
        __syncthreads();

        // gate combine + publish (warp 0 only), then scoped-release grid barrier
        if (warp == 0) {
            if (lane < nj) {
                int jl = lane;
                float gi = (gpart[0][0*JJ+jl] + gpart[1][0*JJ+jl]) + (gpart[2][0*JJ+jl] + gpart[3][0*JJ+jl]) + xwi;
                float gf = (gpart[0][1*JJ+jl] + gpart[1][1*JJ+jl]) + (gpart[2][1*JJ+jl] + gpart[3][1*JJ+jl]) + xwf;
                float gg = (gpart[0][2*JJ+jl] + gpart[1][2*JJ+jl]) + (gpart[2][2*JJ+jl] + gpart[3][2*JJ+jl]) + xwg;
                float go = (gpart[0][3*JJ+jl] + gpart[1][3*JJ+jl]) + (gpart[2][3*JJ+jl] + gpart[3][3*JJ+jl]) + xwo;
                float c = sigmoidf_fast(gf) * cst[jl] + sigmoidf_fast(gi) * tanhf_fast(gg);
                float h = sigmoidf_fast(go) * tanhf_fast(c);
                cst[jl] = c;
                int j = j0 + jl;
                __half hhv = __float2half_rn(h);
                g_hbuf[(t + 1) & 1][j] = hhv;                 // for next step's matvec
                g_hseq[(size_t)t * H2 + j] = hhv;             // for next layer's GEMM
                if (last_layer && t == T_STEPS - 1) g_hlast[j] = h;
            }
            __syncwarp();
            if (lane == 0) grid_sync(++ph, base, cta0);       // release-arrive carries h writes
        }
        __syncthreads();
    }
}

// ---------------- final projection + log_softmax ----------------
__global__ void final_kernel(const float* __restrict__ wout, const float* __restrict__ bout,
                             float* __restrict__ out) {
    int tid = threadIdx.x;
    float s0 = 0.f, s1 = 0.f;
    for (int k = tid; k < H2; k += 256) {
        float h = g_hlast[k];
        s0 = fmaf(h, wout[k], s0);
        s1 = fmaf(h, wout[H2 + k], s1);
    }
    __shared__ float r0[8], r1[8];
#pragma unroll
    for (int o = 16; o; o >>= 1) {
        s0 += __shfl_xor_sync(0xffffffffu, s0, o);
        s1 += __shfl_xor_sync(0xffffffffu, s1, o);
    }
    if ((tid & 31) == 0) { r0[tid >> 5] = s0; r1[tid >> 5] = s1; }
    __syncthreads();
    if (tid == 0) {
        float l0 = bout[0], l1 = bout[1];
        for (int w = 0; w < 8; w++) { l0 += r0[w]; l1 += r1[w]; }
        float m = fmaxf(l0, l1);
        float z = expf(l0 - m) + expf(l1 - m);
        float lse = m + logf(z);
        out[0] = l0 - lse;
        out[1] = l1 - lse;
    }
}

// ---------------- launcher ----------------
extern "C" void kernel_launch(void* const* d_in, const int* in_sizes, int n_in,
                              void* d_out, int out_size) {
    const float* event = (const float*)d_in[0];
    const float* w_ih0 = (const float*)d_in[1];   // (8192, 1)
    const float* w_ih  = (const float*)d_in[2];   // (3, 8192, 2048)
    const float* w_hh  = (const float*)d_in[3];   // (4, 8192, 2048)
    const float* b_ih  = (const float*)d_in[4];   // (4, 8192)
    const float* b_hh  = (const float*)d_in[5];   // (4, 8192)
    const float* w_out = (const float*)d_in[6];   // (2, 2048)
    const float* b_out = (const float*)d_in[7];   // (2,)
    float* out = (float*)d_out;

    cudaFuncSetAttribute(lstm_scan, cudaFuncAttributeMaxDynamicSharedMemorySize, SCAN_SMEM);

    // launch order (for ncu -s 5): pack(0), xw0(1), nop(2), scan_l0(3),
    // gemm_l1(4), scan_l1(5) <- profiled, gemm_l2(6), scan_l2(7), ...
    pack_extra<<<dim3(NCTA, LAYERS), 256>>>(w_hh);

    for (int l = 0; l < LAYERS; ++l) {
        if (l == 0) {
            dim3 grid(NG / (256 * 4), T_STEPS);
            xw0_kernel<<<grid, 256>>>(event, w_ih0, b_ih, b_hh);
            nop_kernel<<<1, 1>>>();
        } else {
            dim3 grid(NG / BN, T_STEPS / BM);
            gemm_xw<<<grid, 256>>>(w_ih + (size_t)(l - 1) * NG * H2,
                                   b_ih + (size_t)l * NG,
                                   b_hh + (size_t)l * NG);
        }
        lstm_scan<<<NCTA, SCAN_THREADS, SCAN_SMEM>>>(w_hh + (size_t)l * NG * H2, l);
    }
    final_kernel<<<1, 256>>>(w_out, b_out, out);
}

// round 13
// speedup vs baseline: 1.2014x; 1.0364x over previous
#include <cuda_runtime.h>
#include <cuda_fp16.h>
#include <math.h>

#define H2 2048
#define T_STEPS 2048
#define NG 8192            // 4*H2
#define LAYERS 4
#define JJ 14              // h-elements per CTA
#define ROWS 56            // 4*JJ gate rows per CTA
#define NCTA 147           // ceil(2048/14)
#define SCAN_THREADS 1024
#define SMEM_ROWS 55                      // rows kept in SMEM (row 55 streamed via L1)
#define SCAN_SMEM (SMEM_ROWS * H2 * 2)    // 225280 bytes of fp16 weights
#define HCOPIES 8                         // h replication factor (cuts per-line L2 drain 8x)

// ---------------- scratch (static device globals; no allocation) ----------------
__device__ float  g_xw[(size_t)T_STEPS * NG];        // 67 MB: xw for current layer
__device__ __align__(16) __half g_hseq[(size_t)T_STEPS * H2]; // h sequence (fp16)
// double-buffered, 8x-replicated h for the scan: copy c read only by CTAs with bid&7==c
__device__ __align__(16) __half g_hrep[2][HCOPIES][H2];
__device__ __align__(16) __half g_wext[(size_t)LAYERS * NCTA * H2]; // per-CTA extra row (fp16)
__device__ float  g_hlast[H2];                       // fp32 h at t=T-1
// barrier state: two parity counters (128B apart) + generation word.
// Counters are reset by CTA0 each phase (end each launch at 0); gen is
// monotone across launches/replays -> graph-replay safe.
__device__ unsigned g_cnt[2 * 32];
__device__ unsigned g_gen2 = 0;

// ---------------- helpers ----------------
static __device__ __forceinline__ float2 h2_to_f2(unsigned u) {
    __half2 h;
    *reinterpret_cast<unsigned*>(&h) = u;
    return __half22float2(h);
}
static __device__ __forceinline__ __half2 u2h2(unsigned u) {
    __half2 h;
    *reinterpret_cast<unsigned*>(&h) = u;
    return h;
}
static __device__ __forceinline__ uint4 ldcg_v4(const uint4* p) {
    uint4 v;
    asm volatile("ld.global.cg.v4.u32 {%0,%1,%2,%3}, [%4];"
                 : "=r"(v.x), "=r"(v.y), "=r"(v.z), "=r"(v.w) : "l"(p));
    return v;
}
static __device__ __forceinline__ unsigned ld_cg_u32(const unsigned* p) {
    unsigned v;
    asm volatile("ld.global.cg.u32 %0, [%1];" : "=r"(v) : "l"(p));
    return v;
}
// scoped memory-model ops: no full MEMBAR anywhere in the sync path
static __device__ __forceinline__ void red_add_release(unsigned* p) {
    asm volatile("red.release.gpu.global.add.u32 [%0], 1;" :: "l"(p) : "memory");
}
static __device__ __forceinline__ unsigned ld_acq(const unsigned* p) {
    unsigned v;
    asm volatile("ld.acquire.gpu.global.u32 %0, [%1];" : "=r"(v) : "l"(p) : "memory");
    return v;
}
static __device__ __forceinline__ void st_rel(unsigned* p, unsigned v) {
    asm volatile("st.release.gpu.global.u32 [%0], %1;" :: "l"(p), "r"(v) : "memory");
}
static __device__ __forceinline__ void st_rlx(unsigned* p, unsigned v) {
    asm volatile("st.relaxed.gpu.global.u32 [%0], %1;" :: "l"(p), "r"(v) : "memory");
}
static __device__ __forceinline__ float sigmoidf_fast(float x) {
    return 1.0f / (1.0f + __expf(-x));
}
static __device__ __forceinline__ float tanhf_fast(float x) {
    return 2.0f / (1.0f + __expf(-2.0f * x)) - 1.0f;
}

// grid barrier, called by thread 0 of each CTA for phase ph (1,2,3,...):
//  - every CTA: fire-and-forget release-arrive on counter[ph&1] (no return wait)
//  - CTA0: acquire-poll the counter to NCTA, reset it, release gen = base+ph
//  - others: acquire-poll gen >= base+ph
// Counter reuse is race-free: counter p is next used at phase p+2, and any
// phase-p+2 arrival happens only after that CTA observed gen >= base+p+1,
// which CTA0 published strictly after resetting counter p.
static __device__ __forceinline__ void grid_sync(unsigned ph, unsigned base, bool cta0) {
    unsigned* cnt = &g_cnt[(ph & 1) * 32];
    red_add_release(cnt);
    if (cta0) {
        int spin = 0;
        while (ld_acq(cnt) < NCTA) { if (++spin > 64) __nanosleep(64); }
        st_rlx(cnt, 0);
        st_rel(&g_gen2, base + ph);
    } else {
        int spin = 0;
        while ((int)(ld_acq(&g_gen2) - (base + ph)) < 0) { if (++spin > 64) __nanosleep(64); }
    }
}

// ---------------- pack per-CTA extra weight row (gate o, jl=13) to fp16 ----------------
__global__ void pack_extra(const float* __restrict__ whh) {
    int k = blockIdx.x;          // CTA index
    int l = blockIdx.y;          // layer
    int j = JJ * k + JJ - 1;     // h index of the extra row
    __half* dst = g_wext + ((size_t)l * NCTA + k) * H2;
    if (j >= H2) {
        for (int i = threadIdx.x; i < H2; i += 256) dst[i] = __float2half(0.0f);
        return;
    }
    const float* src = whh + ((size_t)l * NG + 3 * H2 + j) * H2;
    for (int i = threadIdx.x; i < H2; i += 256) dst[i] = __float2half_rn(src[i]);
}

// ---------------- nop pad so lstm_scan(layer1) lands on ncu's -s 5 capture slot ----
__global__ void nop_kernel() {}

// ---------------- layer-0 xw: xw[t][r] = event[t]*w_ih0[r] + b_ih[r] + b_hh[r] ----------------
__global__ void xw0_kernel(const float* __restrict__ event, const float* __restrict__ w0,
                           const float* __restrict__ bih, const float* __restrict__ bhh) {
    int t = blockIdx.y;
    int c = (blockIdx.x * blockDim.x + threadIdx.x) * 4;
    float e = event[t];
    float4 w  = *(const float4*)(w0 + c);
    float4 bi = *(const float4*)(bih + c);
    float4 bh = *(const float4*)(bhh + c);
    float4 r;
    r.x = fmaf(e, w.x, bi.x + bh.x);
    r.y = fmaf(e, w.y, bi.y + bh.y);
    r.z = fmaf(e, w.z, bi.z + bh.z);
    r.w = fmaf(e, w.w, bi.w + bh.w);
    *(float4*)(g_xw + (size_t)t * NG + c) = r;
}

// ---------------- xw GEMM: g_xw[t][r] = sum_k g_hseq[t][k] * B[r][k] + bias[r] ----------------
#define BM 128
#define BN 128
#define BK 32
#define SPAD 4

__global__ __launch_bounds__(256, 2) void gemm_xw(const float* __restrict__ B,
                                                  const float* __restrict__ bih,
                                                  const float* __restrict__ bhh) {
    __shared__ float As[BK][BM + SPAD];
    __shared__ float Bs[BK][BN + SPAD];
    const int tid = threadIdx.x;
    const int tx = tid & 15;
    const int ty = tid >> 4;
    const int row0 = blockIdx.y * BM;   // t
    const int col0 = blockIdx.x * BN;   // r

    const int lr = tid >> 1;            // 0..127 (tile row for loads)
    const int lc = (tid & 1) * 16;      // 0 or 16 (k offset for loads)
    const __half* aptr = g_hseq + (size_t)(row0 + lr) * H2 + lc;
    const float*  bptr = B      + (size_t)(col0 + lr) * H2 + lc;

    float acc[8][8];
#pragma unroll
    for (int i = 0; i < 8; i++)
#pragma unroll
        for (int j = 0; j < 8; j++) acc[i][j] = 0.0f;

    for (int k0 = 0; k0 < H2; k0 += BK) {
        uint4 a0 = *(const uint4*)(aptr + k0);
        uint4 a1 = *(const uint4*)(aptr + k0 + 8);
        float4 b0 = *(const float4*)(bptr + k0);
        float4 b1 = *(const float4*)(bptr + k0 + 4);
        float4 b2 = *(const float4*)(bptr + k0 + 8);
        float4 b3 = *(const float4*)(bptr + k0 + 12);
        __syncthreads();
        {
            unsigned aw[8] = {a0.x, a0.y, a0.z, a0.w, a1.x, a1.y, a1.z, a1.w};
#pragma unroll
            for (int e = 0; e < 8; e++) {
                float2 f = h2_to_f2(aw[e]);
                As[lc + 2 * e][lr]     = f.x;
                As[lc + 2 * e + 1][lr] = f.y;
            }
            float bw[16] = {b0.x, b0.y, b0.z, b0.w, b1.x, b1.y, b1.z, b1.w,
                            b2.x, b2.y, b2.z, b2.w, b3.x, b3.y, b3.z, b3.w};
#pragma unroll
            for (int e = 0; e < 16; e++) Bs[lc + e][lr] = bw[e];
        }
        __syncthreads();
#pragma unroll
        for (int k = 0; k < BK; k++) {
            float4 xa = *(const float4*)&As[k][ty * 8];
            float4 xb = *(const float4*)&As[k][ty * 8 + 4];
            float4 ya = *(const float4*)&Bs[k][tx * 8];
            float4 yb = *(const float4*)&Bs[k][tx * 8 + 4];
            float av[8] = {xa.x, xa.y, xa.z, xa.w, xb.x, xb.y, xb.z, xb.w};
            float bv[8] = {ya.x, ya.y, ya.z, ya.w, yb.x, yb.y, yb.z, yb.w};
#pragma unroll
            for (int i = 0; i < 8; i++)
#pragma unroll
                for (int j = 0; j < 8; j++) acc[i][j] = fmaf(av[i], bv[j], acc[i][j]);
        }
    }

    float bias[8];
#pragma unroll
    for (int j = 0; j < 8; j++) {
        int c = col0 + tx * 8 + j;
        bias[j] = __ldg(bih + c) + __ldg(bhh + c);
    }
#pragma unroll
    for (int i = 0; i < 8; i++) {
        float* crow = g_xw + (size_t)(row0 + ty * 8 + i) * NG + col0 + tx * 8;
        float4 v0 = {acc[i][0] + bias[0], acc[i][1] + bias[1], acc[i][2] + bias[2], acc[i][3] + bias[3]};
        float4 v1 = {acc[i][4] + bias[4], acc[i][5] + bias[5], acc[i][6] + bias[6], acc[i][7] + bias[7]};
        *(float4*)crow = v0;
        *(float4*)(crow + 4) = v1;
    }
}

// ---------------- persistent LSTM scan (v5: 8x-replicated h exchange) ----------
// Compute core and barrier identical to R12. h publication now writes 8 copies
// (fire-and-forget stores, ordered by the release-arrive); each CTA stages from
// copy bid&7, cutting the per-L2-line request count at step start from
// 147 CTAs x 8 granules = 1176 to ~18 x 8 = 147 (one LTS slice serves each line).
__global__ __launch_bounds__(SCAN_THREADS, 1) void lstm_scan(const float* __restrict__ whh,
                                                             int layer) {
    extern __shared__ __align__(16) unsigned char smem_raw[];
    __half2* wsh = (__half2*)smem_raw;          // SMEM_ROWS x 1024 half2
    __shared__ __align__(16) uint4 h_s[256];    // staged h_{t-1} (4KB)
    __shared__ float gpart[4][ROWS];
    __shared__ float cst[JJ];

    const int tid  = threadIdx.x;
    const int lane = tid & 31;
    const int warp = tid >> 5;
    const int grp  = warp & 7;
    const int kq   = warp >> 3;                 // 0..3
    const int koff = kq * 64;                   // uint4 offset into a 256-uint4 row
    const int j0   = blockIdx.x * JJ;
    const int nj   = (H2 - j0 < JJ) ? (H2 - j0) : JJ;
    const int last_layer = (layer == LAYERS - 1);
    const bool cta0 = (blockIdx.x == 0);
    const int mycpy = blockIdx.x & (HCOPIES - 1);

    unsigned base = 0, ph = 0;
    if (tid == 0) base = ld_cg_u32(&g_gen2);

    // zero this CTA's h slots in all copies of both scan buffers
    if (tid < JJ) {
        int j = j0 + tid;
        if (j < H2) {
            __half z = __float2half(0.0f);
#pragma unroll
            for (int c = 0; c < HCOPIES; c++) {
                g_hrep[0][c][j] = z;
                g_hrep[1][c][j] = z;
            }
        }
    }

    // load + convert this CTA's first 55 weight rows into SMEM (row r = gate*JJ + jl)
    for (int r = warp; r < SMEM_ROWS; r += 32) {
        int gate = r / JJ;
        int jl = r - gate * JJ;
        __half2* dst = wsh + r * (H2 / 2);
        if (jl < nj) {
            const float2* src = (const float2*)(whh + ((size_t)gate * H2 + j0 + jl) * H2);
            for (int p = lane; p < H2 / 2; p += 32) {
                float2 v = __ldg(src + p);
                dst[p] = __floats2half2_rn(v.x, v.y);
            }
        } else {
            for (int p = lane; p < H2 / 2; p += 32) dst[p] = __half2half2(__float2half(0.0f));
        }
    }
    if (tid < JJ) cst[tid] = 0.0f;
    __syncthreads();

    // phase 1: all CTAs' zeroed h slots visible grid-wide
    if (tid == 0) grid_sync(++ph, base, cta0);
    __syncthreads();

    const uint4* wbase = (const uint4*)smem_raw;
    const uint4* wext  = (const uint4*)(g_wext + ((size_t)layer * NCTA + blockIdx.x) * H2);

    for (int t = 0; t < T_STEPS; ++t) {
        // stage h_{t-1} from this CTA's copy: one 16B .cg load per 16B (256 threads)
        if (tid < 256) {
            h_s[tid] = ldcg_v4(((const uint4*)(&g_hrep[t & 1][mycpy][0])) + tid);
        }
        // prefetch xw for this CTA's gate entries (warp 0 lanes; used in combine)
        float xwi = 0.f, xwf = 0.f, xwg = 0.f, xwo = 0.f;
        if (tid < nj) {
            const float* xwt = g_xw + (size_t)t * NG + j0 + tid;
            xwi = __ldg(xwt);
            xwf = __ldg(xwt + H2);
            xwg = __ldg(xwt + 2 * H2);
            xwo = __ldg(xwt + 3 * H2);
        }
        __syncthreads();   // h_s ready

        // this warp's K-quarter of h: 8 half2 regs (broadcast across same-kq warps)
        uint4 hu0 = h_s[koff + lane];
        uint4 hu1 = h_s[koff + lane + 32];
        __half2 hh[8];
        hh[0]=u2h2(hu0.x); hh[1]=u2h2(hu0.y); hh[2]=u2h2(hu0.z); hh[3]=u2h2(hu0.w);
        hh[4]=u2h2(hu1.x); hh[5]=u2h2(hu1.y); hh[6]=u2h2(hu1.z); hh[7]=u2h2(hu1.w);

        // 7 dot-product rows per warp, over this warp's K-quarter
#pragma unroll
        for (int rr = 0; rr < 7; rr++) {
            int r = grp * 7 + rr;
            const uint4* wr = (rr == 6 && grp == 7) ? (wext + koff)
                                                    : (wbase + (size_t)r * 256 + koff);
            uint4 wv0 = wr[lane];
            uint4 wv1 = wr[lane + 32];
            __half2 zero = __half2half2(__float2half(0.0f));
            __half2 a0 = zero, a1 = zero, a2 = zero, a3 = zero;
            a0 = __hfma2(u2h2(wv0.x), hh[0], a0);
            a1 = __hfma2(u2h2(wv0.y), hh[1], a1);
            a2 = __hfma2(u2h2(wv0.z), hh[2], a2);
            a3 = __hfma2(u2h2(wv0.w), hh[3], a3);
            a0 = __hfma2(u2h2(wv1.x), hh[4], a0);
            a1 = __hfma2(u2h2(wv1.y), hh[5], a1);
            a2 = __hfma2(u2h2(wv1.z), hh[6], a2);
            a3 = __hfma2(u2h2(wv1.w), hh[7], a3);
            __half2 s01 = __hadd2(a0, a1);      // each half: 4 products
            __half2 s23 = __hadd2(a2, a3);
            float2 f0 = __half22float2(s01);
            float2 f1 = __half22float2(s23);
            float a = (f0.x + f0.y) + (f1.x + f1.y);
#pragma unroll
            for (int o = 16; o; o >>= 1) a += __shfl_xor_sync(0xffffffffu, a, o);
            if (lane == 0) gpart[kq][r] = a;
        }
        __syncthreads();

        // gate combine + publish to all 8 copies (warp 0 only), then grid barrier
        if (warp == 0) {
            if (lane < nj) {
                int jl = lane;
                float gi = (gpart[0][0*JJ+jl] + gpart[1][0*JJ+jl]) + (gpart[2][0*JJ+jl] + gpart[3][0*JJ+jl]) + xwi;
                float gf = (gpart[0][1*JJ+jl] + gpart[1][1*JJ+jl]) + (gpart[2][1*JJ+jl] + gpart[3][1*JJ+jl]) + xwf;
                float gg = (gpart[0][2*JJ+jl] + gpart[1][2*JJ+jl]) + (gpart[2][2*JJ+jl] + gpart[3][2*JJ+jl]) + xwg;
                float go = (gpart[0][3*JJ+jl] + gpart[1][3*JJ+jl]) + (gpart[2][3*JJ+jl] + gpart[3][3*JJ+jl]) + xwo;
                float c = sigmoidf_fast(gf) * cst[jl] + sigmoidf_fast(gi) * tanhf_fast(gg);
                float h = sigmoidf_fast(go) * tanhf_fast(c);
                cst[jl] = c;
                int j = j0 + jl;
                __half hhv = __float2half_rn(h);
#pragma unroll
                for (int cc = 0; cc < HCOPIES; cc++)
                    g_hrep[(t + 1) & 1][cc][j] = hhv;         // for next step's matvec
                g_hseq[(size_t)t * H2 + j] = hhv;             // for next layer's GEMM
                if (last_layer && t == T_STEPS - 1) g_hlast[j] = h;
            }
            __syncwarp();
            if (lane == 0) grid_sync(++ph, base, cta0);       // release-arrive carries h writes
        }
        __syncthreads();
    }
}

// ---------------- final projection + log_softmax ----------------
__global__ void final_kernel(const float* __restrict__ wout, const float* __restrict__ bout,
                             float* __restrict__ out) {
    int tid = threadIdx.x;
    float s0 = 0.f, s1 = 0.f;
    for (int k = tid; k < H2; k += 256) {
        float h = g_hlast[k];
        s0 = fmaf(h, wout[k], s0);
        s1 = fmaf(h, wout[H2 + k], s1);
    }
    __shared__ float r0[8], r1[8];
#pragma unroll
    for (int o = 16; o; o >>= 1) {
        s0 += __shfl_xor_sync(0xffffffffu, s0, o);
        s1 += __shfl_xor_sync(0xffffffffu, s1, o);
    }
    if ((tid & 31) == 0) { r0[tid >> 5] = s0; r1[tid >> 5] = s1; }
    __syncthreads();
    if (tid == 0) {
        float l0 = bout[0], l1 = bout[1];
        for (int w = 0; w < 8; w++) { l0 += r0[w]; l1 += r1[w]; }
        float m = fmaxf(l0, l1);
        float z = expf(l0 - m) + expf(l1 - m);
        float lse = m + logf(z);
        out[0] = l0 - lse;
        out[1] = l1 - lse;
    }
}

// ---------------- launcher ----------------
extern "C" void kernel_launch(void* const* d_in, const int* in_sizes, int n_in,
                              void* d_out, int out_size) {
    const float* event = (const float*)d_in[0];
    const float* w_ih0 = (const float*)d_in[1];   // (8192, 1)
    const float* w_ih  = (const float*)d_in[2];   // (3, 8192, 2048)
    const float* w_hh  = (const float*)d_in[3];   // (4, 8192, 2048)
    const float* b_ih  = (const float*)d_in[4];   // (4, 8192)
    const float* b_hh  = (const float*)d_in[5];   // (4, 8192)
    const float* w_out = (const float*)d_in[6];   // (2, 2048)
    const float* b_out = (const float*)d_in[7];   // (2,)
    float* out = (float*)d_out;

    cudaFuncSetAttribute(lstm_scan, cudaFuncAttributeMaxDynamicSharedMemorySize, SCAN_SMEM);

    // launch order (for ncu -s 5): pack(0), xw0(1), nop(2), scan_l0(3),
    // gemm_l1(4), scan_l1(5) <- profiled, gemm_l2(6), scan_l2(7), ...
    pack_extra<<<dim3(NCTA, LAYERS), 256>>>(w_hh);

    for (int l = 0; l < LAYERS; ++l) {
        if (l == 0) {
            dim3 grid(NG / (256 * 4), T_STEPS);
            xw0_kernel<<<grid, 256>>>(event, w_ih0, b_ih, b_hh);
            nop_kernel<<<1, 1>>>();
        } else {
            dim3 grid(NG / BN, T_STEPS / BM);
            gemm_xw<<<grid, 256>>>(w_ih + (size_t)(l - 1) * NG * H2,
                                   b_ih + (size_t)l * NG,
                                   b_hh + (size_t)l * NG);
        }
        lstm_scan<<<NCTA, SCAN_THREADS, SCAN_SMEM>>>(w_hh + (size_t)l * NG * H2, l);
    }
    final_kernel<<<1, 256>>>(w_out, b_out, out);
}

// round 14
// speedup vs baseline: 1.3575x; 1.1299x over previous
#include <cuda_runtime.h>
#include <cuda_fp16.h>
#include <math.h>

#define H2 2048
#define T_STEPS 2048
#define NG 8192            // 4*H2
#define LAYERS 4
#define JJ 14              // h-elements per CTA
#define ROWS 56            // 4*JJ gate rows per CTA
#define NCTA 147           // ceil(2048/14)
#define SCAN_THREADS 1024
#define SMEM_ROWS 55                      // rows kept in SMEM (row 55 streamed via L1)
#define SCAN_SMEM (SMEM_ROWS * H2 * 2)    // 225280 bytes of fp16 weights
#define HCOPIES 8                         // h replication factor

// ---------------- scratch (static device globals; no allocation) ----------------
__device__ float  g_xw[(size_t)T_STEPS * NG];        // 67 MB: xw for current layer
__device__ __align__(16) __half g_hseq[(size_t)T_STEPS * H2]; // h sequence (fp16)
// double-buffered, 8x-replicated h for the scan: copy c read only by CTAs with bid&7==c
__device__ __align__(16) __half g_hrep[2][HCOPIES][H2];
__device__ __align__(16) __half g_wext[(size_t)LAYERS * NCTA * H2]; // per-CTA extra row (fp16)
__device__ float  g_hlast[H2];                       // fp32 h at t=T-1
// single-hop barrier state: one counter per step (128B apart) + prologue counter.
// All counters are MONOTONE (+NCTA per scan launch, never reset); g_epoch counts
// completed scan launches. Target for launch E is (E+1)*NCTA. Graph-replay safe.
__device__ unsigned g_steps[T_STEPS * 32];
__device__ unsigned g_zcnt[32];
__device__ unsigned g_epoch = 0;

// ---------------- helpers ----------------
static __device__ __forceinline__ float2 h2_to_f2(unsigned u) {
    __half2 h;
    *reinterpret_cast<unsigned*>(&h) = u;
    return __half22float2(h);
}
static __device__ __forceinline__ __half2 u2h2(unsigned u) {
    __half2 h;
    *reinterpret_cast<unsigned*>(&h) = u;
    return h;
}
static __device__ __forceinline__ uint4 ldcg_v4(const uint4* p) {
    uint4 v;
    asm volatile("ld.global.cg.v4.u32 {%0,%1,%2,%3}, [%4];"
                 : "=r"(v.x), "=r"(v.y), "=r"(v.z), "=r"(v.w) : "l"(p));
    return v;
}
static __device__ __forceinline__ unsigned ld_cg_u32(const unsigned* p) {
    unsigned v;
    asm volatile("ld.global.cg.u32 %0, [%1];" : "=r"(v) : "l"(p));
    return v;
}
// scoped memory-model ops: no full MEMBAR anywhere in the sync path
static __device__ __forceinline__ void red_add_release(unsigned* p) {
    asm volatile("red.release.gpu.global.add.u32 [%0], 1;" :: "l"(p) : "memory");
}
static __device__ __forceinline__ unsigned ld_acq(const unsigned* p) {
    unsigned v;
    asm volatile("ld.acquire.gpu.global.u32 %0, [%1];" : "=r"(v) : "l"(p) : "memory");
    return v;
}
static __device__ __forceinline__ void st_rlx(unsigned* p, unsigned v) {
    asm volatile("st.relaxed.gpu.global.u32 [%0], %1;" :: "l"(p), "r"(v) : "memory");
}
static __device__ __forceinline__ float sigmoidf_fast(float x) {
    return 1.0f / (1.0f + __expf(-x));
}
static __device__ __forceinline__ float tanhf_fast(float x) {
    return 2.0f / (1.0f + __expf(-2.0f * x)) - 1.0f;
}

// single-hop grid barrier on a dedicated per-phase counter:
// fire-and-forget release-arrive, then direct acquire-poll to target.
// (release orders this CTA's prior h stores; acquire orders subsequent h reads)
static __device__ __forceinline__ void step_bar(unsigned* cnt, unsigned target) {
    red_add_release(cnt);
    int spin = 0;
    while ((int)(ld_acq(cnt) - target) < 0) { if (++spin > 64) __nanosleep(64); }
}

// ---------------- pack per-CTA extra weight row (gate o, jl=13) to fp16 ----------------
__global__ void pack_extra(const float* __restrict__ whh) {
    int k = blockIdx.x;          // CTA index
    int l = blockIdx.y;          // layer
    int j = JJ * k + JJ - 1;     // h index of the extra row
    __half* dst = g_wext + ((size_t)l * NCTA + k) * H2;
    if (j >= H2) {
        for (int i = threadIdx.x; i < H2; i += 256) dst[i] = __float2half(0.0f);
        return;
    }
    const float* src = whh + ((size_t)l * NG + 3 * H2 + j) * H2;
    for (int i = threadIdx.x; i < H2; i += 256) dst[i] = __float2half_rn(src[i]);
}

// ---------------- nop pad so lstm_scan(layer1) lands on ncu's -s 5 capture slot ----
__global__ void nop_kernel() {}

// ---------------- layer-0 xw: xw[t][r] = event[t]*w_ih0[r] + b_ih[r] + b_hh[r] ----------------
__global__ void xw0_kernel(const float* __restrict__ event, const float* __restrict__ w0,
                           const float* __restrict__ bih, const float* __restrict__ bhh) {
    int t = blockIdx.y;
    int c = (blockIdx.x * blockDim.x + threadIdx.x) * 4;
    float e = event[t];
    float4 w  = *(const float4*)(w0 + c);
    float4 bi = *(const float4*)(bih + c);
    float4 bh = *(const float4*)(bhh + c);
    float4 r;
    r.x = fmaf(e, w.x, bi.x + bh.x);
    r.y = fmaf(e, w.y, bi.y + bh.y);
    r.z = fmaf(e, w.z, bi.z + bh.z);
    r.w = fmaf(e, w.w, bi.w + bh.w);
    *(float4*)(g_xw + (size_t)t * NG + c) = r;
}

// ---------------- xw GEMM: g_xw[t][r] = sum_k g_hseq[t][k] * B[r][k] + bias[r] ----------------
#define BM 128
#define BN 128
#define BK 32
#define SPAD 4

__global__ __launch_bounds__(256, 2) void gemm_xw(const float* __restrict__ B,
                                                  const float* __restrict__ bih,
                                                  const float* __restrict__ bhh) {
    __shared__ float As[BK][BM + SPAD];
    __shared__ float Bs[BK][BN + SPAD];
    const int tid = threadIdx.x;
    const int tx = tid & 15;
    const int ty = tid >> 4;
    const int row0 = blockIdx.y * BM;   // t
    const int col0 = blockIdx.x * BN;   // r

    const int lr = tid >> 1;            // 0..127 (tile row for loads)
    const int lc = (tid & 1) * 16;      // 0 or 16 (k offset for loads)
    const __half* aptr = g_hseq + (size_t)(row0 + lr) * H2 + lc;
    const float*  bptr = B      + (size_t)(col0 + lr) * H2 + lc;

    float acc[8][8];
#pragma unroll
    for (int i = 0; i < 8; i++)
#pragma unroll
        for (int j = 0; j < 8; j++) acc[i][j] = 0.0f;

    for (int k0 = 0; k0 < H2; k0 += BK) {
        uint4 a0 = *(const uint4*)(aptr + k0);
        uint4 a1 = *(const uint4*)(aptr + k0 + 8);
        float4 b0 = *(const float4*)(bptr + k0);
        float4 b1 = *(const float4*)(bptr + k0 + 4);
        float4 b2 = *(const float4*)(bptr + k0 + 8);
        float4 b3 = *(const float4*)(bptr + k0 + 12);
        __syncthreads();
        {
            unsigned aw[8] = {a0.x, a0.y, a0.z, a0.w, a1.x, a1.y, a1.z, a1.w};
#pragma unroll
            for (int e = 0; e < 8; e++) {
                float2 f = h2_to_f2(aw[e]);
                As[lc + 2 * e][lr]     = f.x;
                As[lc + 2 * e + 1][lr] = f.y;
            }
            float bw[16] = {b0.x, b0.y, b0.z, b0.w, b1.x, b1.y, b1.z, b1.w,
                            b2.x, b2.y, b2.z, b2.w, b3.x, b3.y, b3.z, b3.w};
#pragma unroll
            for (int e = 0; e < 16; e++) Bs[lc + e][lr] = bw[e];
        }
        __syncthreads();
#pragma unroll
        for (int k = 0; k < BK; k++) {
            float4 xa = *(const float4*)&As[k][ty * 8];
            float4 xb = *(const float4*)&As[k][ty * 8 + 4];
            float4 ya = *(const float4*)&Bs[k][tx * 8];
            float4 yb = *(const float4*)&Bs[k][tx * 8 + 4];
            float av[8] = {xa.x, xa.y, xa.z, xa.w, xb.x, xb.y, xb.z, xb.w};
            float bv[8] = {ya.x, ya.y, ya.z, ya.w, yb.x, yb.y, yb.z, yb.w};
#pragma unroll
            for (int i = 0; i < 8; i++)
#pragma unroll
                for (int j = 0; j < 8; j++) acc[i][j] = fmaf(av[i], bv[j], acc[i][j]);
        }
    }

    float bias[8];
#pragma unroll
    for (int j = 0; j < 8; j++) {
        int c = col0 + tx * 8 + j;
        bias[j] = __ldg(bih + c) + __ldg(bhh + c);
    }
#pragma unroll
    for (int i = 0; i < 8; i++) {
        float* crow = g_xw + (size_t)(row0 + ty * 8 + i) * NG + col0 + tx * 8;
        float4 v0 = {acc[i][0] + bias[0], acc[i][1] + bias[1], acc[i][2] + bias[2], acc[i][3] + bias[3]};
        float4 v1 = {acc[i][4] + bias[4], acc[i][5] + bias[5], acc[i][6] + bias[6], acc[i][7] + bias[7]};
        *(float4*)crow = v0;
        *(float4*)(crow + 4) = v1;
    }
}

// ---------------- persistent LSTM scan (v6: pipelined rows + single-hop barrier) ----
// 32 warps: warp = grp + 8*kq over K-quarter kq. Rows grouped 4+3: accumulate
// each group into independent register accumulators, then run the group's SHFL
// reductions interleaved (tail latency paid ~2x/step instead of 7x). Barrier:
// per-step monotone counters, fire-and-forget release-arrive + direct
// acquire-poll (no CTA0 relay).
__global__ __launch_bounds__(SCAN_THREADS, 1) void lstm_scan(const float* __restrict__ whh,
                                                             int layer) {
    extern __shared__ __align__(16) unsigned char smem_raw[];
    __half2* wsh = (__half2*)smem_raw;          // SMEM_ROWS x 1024 half2
    __shared__ __align__(16) uint4 h_s[256];    // staged h_{t-1} (4KB)
    __shared__ float gpart[4][ROWS];
    __shared__ float cst[JJ];

    const int tid  = threadIdx.x;
    const int lane = tid & 31;
    const int warp = tid >> 5;
    const int grp  = warp & 7;
    const int kq   = warp >> 3;                 // 0..3
    const int koff = kq * 64;                   // uint4 offset into a 256-uint4 row
    const int j0   = blockIdx.x * JJ;
    const int nj   = (H2 - j0 < JJ) ? (H2 - j0) : JJ;
    const int last_layer = (layer == LAYERS - 1);
    const bool cta0 = (blockIdx.x == 0);
    const int mycpy = blockIdx.x & (HCOPIES - 1);

    // launch target: all barrier counters gain +NCTA per scan launch (monotone)
    unsigned E = 0, tgt = 0;
    if (tid == 0) {
        E = ld_cg_u32(&g_epoch);
        tgt = (E + 1) * (unsigned)NCTA;
    }

    // zero this CTA's h slots in all copies of both scan buffers
    if (tid < JJ) {
        int j = j0 + tid;
        if (j < H2) {
            __half z = __float2half(0.0f);
#pragma unroll
            for (int c = 0; c < HCOPIES; c++) {
                g_hrep[0][c][j] = z;
                g_hrep[1][c][j] = z;
            }
        }
    }

    // load + convert this CTA's first 55 weight rows into SMEM (row r = gate*JJ + jl)
    for (int r = warp; r < SMEM_ROWS; r += 32) {
        int gate = r / JJ;
        int jl = r - gate * JJ;
        __half2* dst = wsh + r * (H2 / 2);
        if (jl < nj) {
            const float2* src = (const float2*)(whh + ((size_t)gate * H2 + j0 + jl) * H2);
            for (int p = lane; p < H2 / 2; p += 32) {
                float2 v = __ldg(src + p);
                dst[p] = __floats2half2_rn(v.x, v.y);
            }
        } else {
            for (int p = lane; p < H2 / 2; p += 32) dst[p] = __half2half2(__float2half(0.0f));
        }
    }
    if (tid < JJ) cst[tid] = 0.0f;
    __syncthreads();

    // prologue barrier: zeroed h slots visible grid-wide
    if (tid == 0) step_bar(&g_zcnt[0], tgt);
    __syncthreads();

    const uint4* wbase = (const uint4*)smem_raw;
    const uint4* wext  = (const uint4*)(g_wext + ((size_t)layer * NCTA + blockIdx.x) * H2);

    for (int t = 0; t < T_STEPS; ++t) {
        // stage h_{t-1} from this CTA's copy: one 16B .cg load per 16B (256 threads)
        if (tid < 256) {
            h_s[tid] = ldcg_v4(((const uint4*)(&g_hrep[t & 1][mycpy][0])) + tid);
        }
        // prefetch xw for this CTA's gate entries (warp 0 lanes; used in combine)
        float xwi = 0.f, xwf = 0.f, xwg = 0.f, xwo = 0.f;
        if (tid < nj) {
            const float* xwt = g_xw + (size_t)t * NG + j0 + tid;
            xwi = __ldg(xwt);
            xwf = __ldg(xwt + H2);
            xwg = __ldg(xwt + 2 * H2);
            xwo = __ldg(xwt + 3 * H2);
        }
        __syncthreads();   // h_s ready

        // this warp's K-quarter of h: 8 half2 regs (broadcast across same-kq warps)
        uint4 hu0 = h_s[koff + lane];
        uint4 hu1 = h_s[koff + lane + 32];
        __half2 hh[8];
        hh[0]=u2h2(hu0.x); hh[1]=u2h2(hu0.y); hh[2]=u2h2(hu0.z); hh[3]=u2h2(hu0.w);
        hh[4]=u2h2(hu1.x); hh[5]=u2h2(hu1.y); hh[6]=u2h2(hu1.z); hh[7]=u2h2(hu1.w);

        float ared[7];
        // ---- group A: rows 0..3 (independent accumulator chains, then
        //      interleaved SHFL reductions) ----
        {
            __half2 acc[4][4];
#pragma unroll
            for (int rr = 0; rr < 4; rr++) {
                int r = grp * 7 + rr;
                const uint4* wr = wbase + (size_t)r * 256 + koff;
                uint4 wv0 = wr[lane];
                uint4 wv1 = wr[lane + 32];
                acc[rr][0] = __hmul2(u2h2(wv0.x), hh[0]);
                acc[rr][1] = __hmul2(u2h2(wv0.y), hh[1]);
                acc[rr][2] = __hmul2(u2h2(wv0.z), hh[2]);
                acc[rr][3] = __hmul2(u2h2(wv0.w), hh[3]);
                acc[rr][0] = __hfma2(u2h2(wv1.x), hh[4], acc[rr][0]);
                acc[rr][1] = __hfma2(u2h2(wv1.y), hh[5], acc[rr][1]);
                acc[rr][2] = __hfma2(u2h2(wv1.z), hh[6], acc[rr][2]);
                acc[rr][3] = __hfma2(u2h2(wv1.w), hh[7], acc[rr][3]);
            }
#pragma unroll
            for (int rr = 0; rr < 4; rr++) {
                __half2 s01 = __hadd2(acc[rr][0], acc[rr][1]);
                __half2 s23 = __hadd2(acc[rr][2], acc[rr][3]);
                float2 f0 = __half22float2(s01);
                float2 f1 = __half22float2(s23);
                ared[rr] = (f0.x + f0.y) + (f1.x + f1.y);
            }
#pragma unroll
            for (int o = 16; o; o >>= 1) {
                ared[0] += __shfl_xor_sync(0xffffffffu, ared[0], o);
                ared[1] += __shfl_xor_sync(0xffffffffu, ared[1], o);
                ared[2] += __shfl_xor_sync(0xffffffffu, ared[2], o);
                ared[3] += __shfl_xor_sync(0xffffffffu, ared[3], o);
            }
        }
        // ---- group B: rows 4..6 ----
        {
            __half2 acc[3][4];
#pragma unroll
            for (int rr = 0; rr < 3; rr++) {
                int r = grp * 7 + 4 + rr;
                const uint4* wr = (rr == 2 && grp == 7) ? (wext + koff)
                                                        : (wbase + (size_t)r * 256 + koff);
                uint4 wv0 = wr[lane];
                uint4 wv1 = wr[lane + 32];
                acc[rr][0] = __hmul2(u2h2(wv0.x), hh[0]);
                acc[rr][1] = __hmul2(u2h2(wv0.y), hh[1]);
                acc[rr][2] = __hmul2(u2h2(wv0.z), hh[2]);
                acc[rr][3] = __hmul2(u2h2(wv0.w), hh[3]);
                acc[rr][0] = __hfma2(u2h2(wv1.x), hh[4], acc[rr][0]);
                acc[rr][1] = __hfma2(u2h2(wv1.y), hh[5], acc[rr][1]);
                acc[rr][2] = __hfma2(u2h2(wv1.z), hh[6], acc[rr][2]);
                acc[rr][3] = __hfma2(u2h2(wv1.w), hh[7], acc[rr][3]);
            }
#pragma unroll
            for (int rr = 0; rr < 3; rr++) {
                __half2 s01 = __hadd2(acc[rr][0], acc[rr][1]);
                __half2 s23 = __hadd2(acc[rr][2], acc[rr][3]);
                float2 f0 = __half22float2(s01);
                float2 f1 = __half22float2(s23);
                ared[4 + rr] = (f0.x + f0.y) + (f1.x + f1.y);
            }
#pragma unroll
            for (int o = 16; o; o >>= 1) {
                ared[4] += __shfl_xor_sync(0xffffffffu, ared[4], o);
                ared[5] += __shfl_xor_sync(0xffffffffu, ared[5], o);
                ared[6] += __shfl_xor_sync(0xffffffffu, ared[6], o);
            }
        }
        if (lane == 0) {
#pragma unroll
            for (int rr = 0; rr < 7; rr++) gpart[kq][grp * 7 + rr] = ared[rr];
        }
        __syncthreads();

        // gate combine + publish to all 8 copies (warp 0 only), then grid barrier
        if (warp == 0) {
            if (lane < nj) {
                int jl = lane;
                float gi = (gpart[0][0*JJ+jl] + gpart[1][0*JJ+jl]) + (gpart[2][0*JJ+jl] + gpart[3][0*JJ+jl]) + xwi;
                float gf = (gpart[0][1*JJ+jl] + gpart[1][1*JJ+jl]) + (gpart[2][1*JJ+jl] + gpart[3][1*JJ+jl]) + xwf;
                float gg = (gpart[0][2*JJ+jl] + gpart[1][2*JJ+jl]) + (gpart[2][2*JJ+jl] + gpart[3][2*JJ+jl]) + xwg;
                float go = (gpart[0][3*JJ+jl] + gpart[1][3*JJ+jl]) + (gpart[2][3*JJ+jl] + gpart[3][3*JJ+jl]) + xwo;
                float c = sigmoidf_fast(gf) * cst[jl] + sigmoidf_fast(gi) * tanhf_fast(gg);
                float h = sigmoidf_fast(go) * tanhf_fast(c);
                cst[jl] = c;
                int j = j0 + jl;
                __half hhv = __float2half_rn(h);
#pragma unroll
                for (int cc = 0; cc < HCOPIES; cc++)
                    g_hrep[(t + 1) & 1][cc][j] = hhv;         // for next step's matvec
                g_hseq[(size_t)t * H2 + j] = hhv;             // for next layer's GEMM
                if (last_layer && t == T_STEPS - 1) g_hlast[j] = h;
            }
            __syncwarp();
            if (lane == 0) step_bar(&g_steps[t * 32], tgt);   // release-arrive carries h writes
        }
        __syncthreads();
    }

    // bump the launch epoch (exactly one thread grid-wide; all CTAs read E at start)
    if (cta0 && tid == 0) st_rlx(&g_epoch, E + 1);
}

// ---------------- final projection + log_softmax ----------------
__global__ void final_kernel(const float* __restrict__ wout, const float* __restrict__ bout,
                             float* __restrict__ out) {
    int tid = threadIdx.x;
    float s0 = 0.f, s1 = 0.f;
    for (int k = tid; k < H2; k += 256) {
        float h = g_hlast[k];
        s0 = fmaf(h, wout[k], s0);
        s1 = fmaf(h, wout[H2 + k], s1);
    }
    __shared__ float r0[8], r1[8];
#pragma unroll
    for (int o = 16; o; o >>= 1) {
        s0 += __shfl_xor_sync(0xffffffffu, s0, o);
        s1 += __shfl_xor_sync(0xffffffffu, s1, o);
    }
    if ((tid & 31) == 0) { r0[tid >> 5] = s0; r1[tid >> 5] = s1; }
    __syncthreads();
    if (tid == 0) {
        float l0 = bout[0], l1 = bout[1];
        for (int w = 0; w < 8; w++) { l0 += r0[w]; l1 += r1[w]; }
        float m = fmaxf(l0, l1);
        float z = expf(l0 - m) + expf(l1 - m);
        float lse = m + logf(z);
        out[0] = l0 - lse;
        out[1] = l1 - lse;
    }
}

// ---------------- launcher ----------------
extern "C" void kernel_launch(void* const* d_in, const int* in_sizes, int n_in,
                              void* d_out, int out_size) {
    const float* event = (const float*)d_in[0];
    const float* w_ih0 = (const float*)d_in[1];   // (8192, 1)
    const float* w_ih  = (const float*)d_in[2];   // (3, 8192, 2048)
    const float* w_hh  = (const float*)d_in[3];   // (4, 8192, 2048)
    const float* b_ih  = (const float*)d_in[4];   // (4, 8192)
    const float* b_hh  = (const float*)d_in[5];   // (4, 8192)
    const float* w_out = (const float*)d_in[6];   // (2, 2048)
    const float* b_out = (const float*)d_in[7];   // (2,)
    float* out = (float*)d_out;

    cudaFuncSetAttribute(lstm_scan, cudaFuncAttributeMaxDynamicSharedMemorySize, SCAN_SMEM);

    // launch order (for ncu -s 5): pack(0), xw0(1), nop(2), scan_l0(3),
    // gemm_l1(4), scan_l1(5) <- profiled, gemm_l2(6), scan_l2(7), ...
    pack_extra<<<dim3(NCTA, LAYERS), 256>>>(w_hh);

    for (int l = 0; l < LAYERS; ++l) {
        if (l == 0) {
            dim3 grid(NG / (256 * 4), T_STEPS);
            xw0_kernel<<<grid, 256>>>(event, w_ih0, b_ih, b_hh);
            nop_kernel<<<1, 1>>>();
        } else {
            dim3 grid(NG / BN, T_STEPS / BM);
            gemm_xw<<<grid, 256>>>(w_ih + (size_t)(l - 1) * NG * H2,
                                   b_ih + (size_t)l * NG,
                                   b_hh + (size_t)l * NG);
        }
        lstm_scan<<<NCTA, SCAN_THREADS, SCAN_SMEM>>>(w_hh + (size_t)l * NG * H2, l);
    }
    final_kernel<<<1, 256>>>(w_out, b_out, out);
}